// round 4
// baseline (speedup 1.0000x reference)
#include <cuda_runtime.h>
#include <cstdint>

#define NPTS  4096
#define BATCH 8
#define KNN_K 16

// scratch: neighbor indices (original within-batch indices), 2MB
__device__ int g_idx[BATCH * NPTS * KNN_K];
// scratch: per-batch points sorted by x: (x, y, sq, orig_idx_bits), 512KB
__device__ float4 g_sorted[BATCH * NPTS];

// ---------------------------------------------------------------------------
// packed f32x2 helpers
// ---------------------------------------------------------------------------
__device__ __forceinline__ unsigned long long ffma2(unsigned long long a,
                                                    unsigned long long b,
                                                    unsigned long long c) {
    unsigned long long d;
    asm("fma.rn.f32x2 %0, %1, %2, %3;" : "=l"(d) : "l"(a), "l"(b), "l"(c));
    return d;
}
__device__ __forceinline__ unsigned long long add2(unsigned long long a,
                                                   unsigned long long b) {
    unsigned long long d;
    asm("add.rn.f32x2 %0, %1, %2;" : "=l"(d) : "l"(a), "l"(b));
    return d;
}
__device__ __forceinline__ unsigned long long pack2(float lo, float hi) {
    unsigned long long p;
    asm("mov.b64 %0, {%1, %2};" : "=l"(p) : "f"(lo), "f"(hi));
    return p;
}
__device__ __forceinline__ void unpack2(unsigned long long p, float& lo, float& hi) {
    asm("mov.b64 {%0, %1}, %2;" : "=f"(lo), "=f"(hi) : "l"(p));
}

// ---------------------------------------------------------------------------
// Kernel 0: per-batch bitonic sort by x. One block per batch.
// ---------------------------------------------------------------------------
extern "C" __global__ void __launch_bounds__(1024)
sort_kernel(const float* __restrict__ x) {
    extern __shared__ __align__(16) char smem_raw[];
    float4* sp = (float4*)smem_raw;   // 64KB

    const int tid = threadIdx.x;
    const int b   = blockIdx.x;
    const float2* __restrict__ xb = ((const float2*)x) + (size_t)b * NPTS;

    for (int i = tid; i < NPTS; i += 1024) {
        float2 v = xb[i];
        sp[i] = make_float4(v.x, v.y, 0.0f, __int_as_float(i));
    }
    __syncthreads();

    for (int k = 2; k <= NPTS; k <<= 1) {
        for (int j = k >> 1; j > 0; j >>= 1) {
#pragma unroll 4
            for (int i = tid; i < NPTS; i += 1024) {
                int ixj = i ^ j;
                if (ixj > i) {
                    float4 a = sp[i], c = sp[ixj];
                    bool up = ((i & k) == 0);
                    if ((a.x > c.x) == up) { sp[i] = c; sp[ixj] = a; }
                }
            }
            __syncthreads();
        }
    }

    for (int i = tid; i < NPTS; i += 1024) {
        float4 v = sp[i];
        // sq computed with the exact same ops as the distance formula expects
        v.z = __fadd_rn(__fmul_rn(v.x, v.x), __fmul_rn(v.y, v.y));
        g_sorted[(size_t)b * NPTS + i] = v;
    }
}

// ---------------------------------------------------------------------------
// Kernel 1: exact KNN via sorted-x two-pointer scan with dx^2 pruning.
// Key = (monotone-mapped ref distance << 32) | orig_idx  -> exact top_k order.
// ---------------------------------------------------------------------------
extern "C" __global__ void __launch_bounds__(128)
knn_kernel() {
    extern __shared__ __align__(16) char smem_raw[];
    float4* pts = (float4*)smem_raw;              // 64KB (x,y,sq,idbits) sorted
    float*  sx  = (float*)(smem_raw + NPTS * 16); // 16KB x only (stride-4B reads)

    const int tid = threadIdx.x;
    const int b   = blockIdx.y;

    for (int i = tid; i < NPTS; i += 128) {
        float4 v = g_sorted[(size_t)b * NPTS + i];
        pts[i] = v;
        sx[i]  = v.x;
    }
    __syncthreads();

    const int p = blockIdx.x * 128 + tid;         // sorted position of query
    const float4 qp = pts[p];
    const float qx = qp.x, qy = qp.y, qsq = qp.z;
    const int qi = __float_as_int(qp.w);

    unsigned long long heap[KNN_K];
#pragma unroll
    for (int s = 0; s < KNN_K; ++s) heap[s] = ~0ULL;

    const float INF    = __int_as_float(0x7F800000);
    const float MARGIN = 1e-4f;                   // covers distance-formula rounding
    float worstf = INF;                           // prune bound (NaN-safe while filling)

    int l = p;                                    // start at self (dl = 0)
    int r = p + 1;

#pragma unroll 1
    for (;;) {
        if (l < 0 && r >= NPTS) break;
        float dl = (l >= 0)   ? (qx - sx[l]) : INF;
        float dr = (r < NPTS) ? (sx[r] - qx) : INF;
        float dmin = fminf(dl, dr);
        if (dmin * dmin > worstf) break;          // false on NaN -> keep scanning

        int j;
        if (dl <= dr) { j = l; --l; } else { j = r; ++r; }

        float4 pj = pts[j];
        // exact reference formula, no FMA contraction
        float dot = __fadd_rn(__fmul_rn(qx, pj.x), __fmul_rn(qy, pj.y));
        float d   = __fsub_rn(__fadd_rn(qsq, pj.z), __fmul_rn(2.0f, dot));
        int ib = __float_as_int(d);
        unsigned u = (ib >= 0) ? ((unsigned)ib ^ 0x80000000u) : ~(unsigned)ib;
        unsigned long long key =
            ((unsigned long long)u << 32) | (unsigned)__float_as_int(pj.w);

        if (key < heap[KNN_K - 1]) {
            bool c[KNN_K];
#pragma unroll
            for (int s = 0; s < KNN_K; ++s) c[s] = (key < heap[s]);
#pragma unroll
            for (int s = KNN_K - 1; s >= 1; --s)
                heap[s] = c[s - 1] ? heap[s - 1] : (c[s] ? key : heap[s]);
            if (c[0]) heap[0] = key;
            // refresh bound from new 16th key (NaN while heap not yet full)
            unsigned u15 = (unsigned)(heap[KNN_K - 1] >> 32);
            unsigned fb  = (u15 & 0x80000000u) ? (u15 ^ 0x80000000u) : ~u15;
            worstf = __uint_as_float(fb) + MARGIN;
        }
    }

    int* outp = g_idx + ((size_t)b * NPTS + qi) * KNN_K;
#pragma unroll
    for (int s = 0; s < KNN_K; ++s)
        outp[s] = (int)(heap[s] & 0xFFFFFFFFu);
}

// ---------------------------------------------------------------------------
// Kernel 2: fused MLP chain + pooling + final layer + L2 normalize
// (byte-identical to round 3)
// ---------------------------------------------------------------------------
struct __align__(16) SmemMLP {
    float2 pts[NPTS];          // 32KB
    float w1[32];              // [8][4]
    float w2[64];              // [8][8]
    float w3[128];             // [16][8]
    float w4[1024];            // [64][16]
    float w5[9216];            // [96][96]
    float mw[64];              // [4][16]
    float mb[4];
    float s1[8],  b1[8];
    float s2[8],  b2[8];
    float s3[16], b3[16];
    float s4[64], b4[64];
    float s5[96], b5[96];
};

extern "C" __global__ void __launch_bounds__(128)
mlp_kernel(const float* __restrict__ x,
           const float* __restrict__ w1, const float* __restrict__ w2,
           const float* __restrict__ w3, const float* __restrict__ w4,
           const float* __restrict__ w5,
           const float* __restrict__ mw, const float* __restrict__ mb,
           const float* __restrict__ bn1, const float* __restrict__ bn2,
           const float* __restrict__ bn3, const float* __restrict__ bn4,
           const float* __restrict__ bn5,
           float* __restrict__ out) {
    extern __shared__ __align__(16) char smem_raw[];
    SmemMLP* sm = (SmemMLP*)smem_raw;

    const int tid = threadIdx.x;
    const int b   = blockIdx.y;

    // cooperative loads
    for (int i = tid; i < NPTS; i += 128) sm->pts[i] = ((const float2*)x)[(size_t)b * NPTS + i];
    for (int i = tid; i < 32;   i += 128) sm->w1[i] = w1[i];
    for (int i = tid; i < 64;   i += 128) sm->w2[i] = w2[i];
    for (int i = tid; i < 128;  i += 128) sm->w3[i] = w3[i];
    for (int i = tid; i < 1024; i += 128) sm->w4[i] = w4[i];
    for (int i = tid; i < 9216; i += 128) sm->w5[i] = w5[i];
    for (int i = tid; i < 64;   i += 128) sm->mw[i] = mw[i];
    if (tid < 4) sm->mb[tid] = mb[tid];
    // fold BN: scale = gamma*rsqrt(var+eps); bias = beta - mean*scale
    for (int i = tid; i < 8;  i += 128) {
        float s = bn1[i] * rsqrtf(bn1[24 + i] + 1e-5f);
        sm->s1[i] = s; sm->b1[i] = bn1[8 + i] - bn1[16 + i] * s;
        float t = bn2[i] * rsqrtf(bn2[24 + i] + 1e-5f);
        sm->s2[i] = t; sm->b2[i] = bn2[8 + i] - bn2[16 + i] * t;
    }
    for (int i = tid; i < 16; i += 128) {
        float s = bn3[i] * rsqrtf(bn3[48 + i] + 1e-5f);
        sm->s3[i] = s; sm->b3[i] = bn3[16 + i] - bn3[32 + i] * s;
    }
    for (int i = tid; i < 64; i += 128) {
        float s = bn4[i] * rsqrtf(bn4[192 + i] + 1e-5f);
        sm->s4[i] = s; sm->b4[i] = bn4[64 + i] - bn4[128 + i] * s;
    }
    for (int i = tid; i < 96; i += 128) {
        float s = bn5[i] * rsqrtf(bn5[288 + i] + 1e-5f);
        sm->s5[i] = s; sm->b5[i] = bn5[96 + i] - bn5[192 + i] * s;
    }
    __syncthreads();

    const int n  = blockIdx.x * 128 + tid;
    const int gq = b * NPTS + n;
    const int* __restrict__ gi = g_idx + (size_t)gq * KNN_K;

    // packed f32x2 pooled-feature accumulators: f[i] holds features (2i, 2i+1)
    unsigned long long f[48];
#pragma unroll
    for (int i = 0; i < 48; ++i) f[i] = 0ULL;

    const float2 ctr = sm->pts[n];

#pragma unroll 1
    for (int k = 0; k < KNN_K; ++k) {
        const int nbk = gi[k];
        const float2 P = sm->pts[nbk];
        const unsigned long long m1p = pack2(sm->mw[k],      sm->mw[k]);
        const unsigned long long m2p = pack2(sm->mw[16 + k], sm->mw[16 + k]);
        const unsigned long long m3p = pack2(sm->mw[32 + k], sm->mw[32 + k]);
        const unsigned long long m4p = pack2(sm->mw[48 + k], sm->mw[48 + k]);

        // layer 1: 4 -> 8
        float h1[8];
#pragma unroll
        for (int o = 0; o < 8; o += 2) {
#pragma unroll
            for (int t = 0; t < 2; ++t) {
                float4 w = *(const float4*)(sm->w1 + (o + t) * 4);
                float v = P.x * w.x + P.y * w.y + ctr.x * w.z + ctr.y * w.w;
                h1[o + t] = fmaxf(fmaf(v, sm->s1[o + t], sm->b1[o + t]), 0.0f);
            }
            f[o / 2] = ffma2(pack2(h1[o], h1[o + 1]), m1p, f[o / 2]);
        }
        // layer 2: 8 -> 8
        float h2[8];
#pragma unroll
        for (int o = 0; o < 8; o += 2) {
#pragma unroll
            for (int t = 0; t < 2; ++t) {
                const float4* w = (const float4*)(sm->w2 + (o + t) * 8);
                float4 wa = w[0], wb = w[1];
                float v = h1[0] * wa.x + h1[1] * wa.y + h1[2] * wa.z + h1[3] * wa.w
                        + h1[4] * wb.x + h1[5] * wb.y + h1[6] * wb.z + h1[7] * wb.w;
                h2[o + t] = fmaxf(fmaf(v, sm->s2[o + t], sm->b2[o + t]), 0.0f);
            }
            f[4 + o / 2] = ffma2(pack2(h2[o], h2[o + 1]), m2p, f[4 + o / 2]);
        }
        // layer 3: 8 -> 16, stored packed in pairs for layer-4 f32x2 dots
        unsigned long long h3p[8];
#pragma unroll
        for (int o = 0; o < 16; o += 2) {
            float vv[2];
#pragma unroll
            for (int t = 0; t < 2; ++t) {
                const float4* w = (const float4*)(sm->w3 + (o + t) * 8);
                float4 wa = w[0], wb = w[1];
                float v = h2[0] * wa.x + h2[1] * wa.y + h2[2] * wa.z + h2[3] * wa.w
                        + h2[4] * wb.x + h2[5] * wb.y + h2[6] * wb.z + h2[7] * wb.w;
                vv[t] = fmaxf(fmaf(v, sm->s3[o + t], sm->b3[o + t]), 0.0f);
            }
            h3p[o / 2] = pack2(vv[0], vv[1]);
            f[8 + o / 2] = ffma2(h3p[o / 2], m3p, f[8 + o / 2]);
        }
        // layer 4: 16 -> 64 (packed f32x2 dot16)
#pragma unroll 1
        for (int o = 0; o < 64; o += 2) {
            float vv[2];
#pragma unroll
            for (int t = 0; t < 2; ++t) {
                const ulonglong2* wrow = (const ulonglong2*)(sm->w4 + (o + t) * 16);
                ulonglong2 wa = wrow[0], wb = wrow[1], wc = wrow[2], wd = wrow[3];
                unsigned long long acc = ffma2(h3p[0], wa.x, 0ULL);
                acc = ffma2(h3p[1], wa.y, acc);
                acc = ffma2(h3p[2], wb.x, acc);
                acc = ffma2(h3p[3], wb.y, acc);
                acc = ffma2(h3p[4], wc.x, acc);
                acc = ffma2(h3p[5], wc.y, acc);
                acc = ffma2(h3p[6], wd.x, acc);
                acc = ffma2(h3p[7], wd.y, acc);
                float lo, hi; unpack2(acc, lo, hi);
                float v = lo + hi;
                vv[t] = fmaxf(fmaf(v, sm->s4[o + t], sm->b4[o + t]), 0.0f);
            }
            f[16 + o / 2] = ffma2(pack2(vv[0], vv[1]), m4p, f[16 + o / 2]);
        }
    }

    // mlp biases (per segment scalar, pair-aligned segments)
    {
        const unsigned long long c0 = pack2(sm->mb[0], sm->mb[0]);
        const unsigned long long c1 = pack2(sm->mb[1], sm->mb[1]);
        const unsigned long long c2 = pack2(sm->mb[2], sm->mb[2]);
        const unsigned long long c3 = pack2(sm->mb[3], sm->mb[3]);
#pragma unroll
        for (int i = 0; i < 4; ++i)  f[i]      = add2(f[i], c0);
#pragma unroll
        for (int i = 0; i < 4; ++i)  f[4 + i]  = add2(f[4 + i], c1);
#pragma unroll
        for (int i = 0; i < 8; ++i)  f[8 + i]  = add2(f[8 + i], c2);
#pragma unroll
        for (int i = 0; i < 32; ++i) f[16 + i] = add2(f[16 + i], c3);
    }

    // final 96x96 layer: 2 outputs per body, 4 independent ffma2 chains
    float* __restrict__ outp = out + (size_t)gq * 96;
    float ss = 0.0f;
#pragma unroll 1
    for (int o = 0; o < 96; o += 2) {
        const ulonglong2* wA = (const ulonglong2*)(sm->w5 + o * 96);
        const ulonglong2* wB = (const ulonglong2*)(sm->w5 + (o + 1) * 96);
        unsigned long long a0 = 0ULL, a1 = 0ULL, b0 = 0ULL, b1 = 0ULL;
#pragma unroll 6
        for (int j = 0; j < 24; ++j) {
            ulonglong2 wa = wA[j];
            ulonglong2 wb = wB[j];
            a0 = ffma2(f[2 * j],     wa.x, a0);
            a1 = ffma2(f[2 * j + 1], wa.y, a1);
            b0 = ffma2(f[2 * j],     wb.x, b0);
            b1 = ffma2(f[2 * j + 1], wb.y, b1);
        }
        unsigned long long accA = add2(a0, a1);
        unsigned long long accB = add2(b0, b1);
        float lo, hi;
        unpack2(accA, lo, hi);
        float vA = lo + hi;
        unpack2(accB, lo, hi);
        float vB = lo + hi;
        vA = fmaxf(fmaf(vA, sm->s5[o],     sm->b5[o]),     0.0f);
        vB = fmaxf(fmaf(vB, sm->s5[o + 1], sm->b5[o + 1]), 0.0f);
        ss = fmaf(vA, vA, ss);
        ss = fmaf(vB, vB, ss);
        outp[o]     = vA;
        outp[o + 1] = vB;
    }

    const float rn = rsqrtf(ss);
    float4* o4 = (float4*)outp;
#pragma unroll 4
    for (int i = 0; i < 24; ++i) {
        float4 v = o4[i];
        v.x *= rn; v.y *= rn; v.z *= rn; v.w *= rn;
        o4[i] = v;
    }
}

// ---------------------------------------------------------------------------
// launch
// ---------------------------------------------------------------------------
extern "C" void kernel_launch(void* const* d_in, const int* in_sizes, int n_in,
                              void* d_out, int out_size) {
    const float* x   = (const float*)d_in[0];
    const float* w1  = (const float*)d_in[1];
    const float* w2  = (const float*)d_in[2];
    const float* w3  = (const float*)d_in[3];
    const float* w4  = (const float*)d_in[4];
    const float* w5  = (const float*)d_in[5];
    const float* mw  = (const float*)d_in[6];
    const float* mb  = (const float*)d_in[7];
    const float* bn1 = (const float*)d_in[8];
    const float* bn2 = (const float*)d_in[9];
    const float* bn3 = (const float*)d_in[10];
    const float* bn4 = (const float*)d_in[11];
    const float* bn5 = (const float*)d_in[12];

    const size_t sort_smem = NPTS * sizeof(float4);                   // 64KB
    const size_t knn_smem  = NPTS * sizeof(float4) + NPTS * 4;        // 80KB
    const size_t mlp_smem  = sizeof(SmemMLP);                         // ~75KB

    cudaFuncSetAttribute(sort_kernel, cudaFuncAttributeMaxDynamicSharedMemorySize, (int)sort_smem);
    cudaFuncSetAttribute(knn_kernel,  cudaFuncAttributeMaxDynamicSharedMemorySize, (int)knn_smem);
    cudaFuncSetAttribute(mlp_kernel,  cudaFuncAttributeMaxDynamicSharedMemorySize, (int)mlp_smem);

    dim3 grid(NPTS / 128, BATCH);
    sort_kernel<<<BATCH, 1024, sort_smem>>>(x);
    knn_kernel<<<grid, 128, knn_smem>>>();
    mlp_kernel<<<grid, 128, mlp_smem>>>(x, w1, w2, w3, w4, w5, mw, mb,
                                        bn1, bn2, bn3, bn4, bn5, (float*)d_out);
}

// round 5
// speedup vs baseline: 1.2800x; 1.2800x over previous
#include <cuda_runtime.h>
#include <cstdint>

#define NPTS  4096
#define BATCH 8
#define KNN_K 16

// scratch: neighbor indices (original within-batch indices), 2MB
__device__ int g_idx[BATCH * NPTS * KNN_K];
// scratch: per-batch points sorted by x: (x, y, sq, orig_idx_bits), 512KB
__device__ float4 g_sorted[BATCH * NPTS];

// ---------------------------------------------------------------------------
// packed f32x2 helpers
// ---------------------------------------------------------------------------
__device__ __forceinline__ unsigned long long ffma2(unsigned long long a,
                                                    unsigned long long b,
                                                    unsigned long long c) {
    unsigned long long d;
    asm("fma.rn.f32x2 %0, %1, %2, %3;" : "=l"(d) : "l"(a), "l"(b), "l"(c));
    return d;
}
__device__ __forceinline__ unsigned long long add2(unsigned long long a,
                                                   unsigned long long b) {
    unsigned long long d;
    asm("add.rn.f32x2 %0, %1, %2;" : "=l"(d) : "l"(a), "l"(b));
    return d;
}
__device__ __forceinline__ unsigned long long pack2(float lo, float hi) {
    unsigned long long p;
    asm("mov.b64 %0, {%1, %2};" : "=l"(p) : "f"(lo), "f"(hi));
    return p;
}
__device__ __forceinline__ void unpack2(unsigned long long p, float& lo, float& hi) {
    asm("mov.b64 {%0, %1}, %2;" : "=f"(lo), "=f"(hi) : "l"(p));
}

// ---------------------------------------------------------------------------
// Kernel 0: per-batch bitonic sort by x. u64 keys (x monotone bits, idx).
// One block per batch, 32KB smem.
// ---------------------------------------------------------------------------
extern "C" __global__ void __launch_bounds__(1024)
sort_kernel(const float* __restrict__ x) {
    extern __shared__ __align__(16) char smem_raw[];
    unsigned long long* keys = (unsigned long long*)smem_raw;   // 32KB

    const int tid = threadIdx.x;
    const int b   = blockIdx.x;
    const float2* __restrict__ xb = ((const float2*)x) + (size_t)b * NPTS;

    for (int i = tid; i < NPTS; i += 1024) {
        float2 v = xb[i];
        int ib = __float_as_int(v.x);
        unsigned mx = (ib >= 0) ? ((unsigned)ib ^ 0x80000000u) : ~(unsigned)ib;
        keys[i] = ((unsigned long long)mx << 32) | (unsigned)i;
    }
    __syncthreads();

    for (int k = 2; k <= NPTS; k <<= 1) {
        for (int j = k >> 1; j > 0; j >>= 1) {
#pragma unroll 2
            for (int t = tid; t < NPTS / 2; t += 1024) {
                int i  = 2 * t - (t & (j - 1));
                int ix = i + j;
                unsigned long long a = keys[i], c = keys[ix];
                bool up = ((i & k) == 0);
                if ((a > c) == up) { keys[i] = c; keys[ix] = a; }
            }
            __syncthreads();
        }
    }

    for (int i = tid; i < NPTS; i += 1024) {
        unsigned long long kv = keys[i];
        int idx = (int)(kv & 0xFFFFFFFFu);
        float2 v = xb[idx];
        float sq = __fadd_rn(__fmul_rn(v.x, v.x), __fmul_rn(v.y, v.y));
        g_sorted[(size_t)b * NPTS + i] = make_float4(v.x, v.y, sq, __int_as_float(idx));
    }
}

// ---------------------------------------------------------------------------
// Kernel 1: exact KNN on sorted-x data, UNIFORM outward offset scan.
// All lanes share the offset schedule d=1,2,... (chunks of 8), with per-lane
// predication at array edges; warp-vote early exit when every lane's next
// |dx|^2 exceeds its 16th-best distance + margin.
// Key = (monotone-mapped ref distance << 32) | orig_idx -> exact top_k order,
// invariant to scan order (identical logic to validated round-4 version).
// ---------------------------------------------------------------------------
extern "C" __global__ void __launch_bounds__(128)
knn_kernel() {
    extern __shared__ __align__(16) char smem_raw[];
    float4* pts = (float4*)smem_raw;              // 64KB (x,y,sq,idbits) sorted

    const int tid = threadIdx.x;
    const int b   = blockIdx.y;

    for (int i = tid; i < NPTS; i += 128)
        pts[i] = g_sorted[(size_t)b * NPTS + i];
    __syncthreads();

    const int p = blockIdx.x * 128 + tid;         // sorted position of query
    const float4 qp = pts[p];
    const float qx = qp.x, qy = qp.y, qsq = qp.z;
    const int qi = __float_as_int(qp.w);

    unsigned long long heap[KNN_K];
#pragma unroll
    for (int s = 0; s < KNN_K; ++s) heap[s] = ~0ULL;

    const float INF    = __int_as_float(0x7F800000);
    const float MARGIN = 1e-4f;                   // covers distance-formula rounding
    float worstf = INF;

    // candidate processing (shared by self + offset scan)
    auto process = [&](int j, bool valid) {
        int jc = valid ? j : p;                   // safe in-range load
        float4 pj = pts[jc];
        // exact reference formula, no FMA contraction
        float dot = __fadd_rn(__fmul_rn(qx, pj.x), __fmul_rn(qy, pj.y));
        float d   = __fsub_rn(__fadd_rn(qsq, pj.z), __fmul_rn(2.0f, dot));
        int ib = __float_as_int(d);
        unsigned u = (ib >= 0) ? ((unsigned)ib ^ 0x80000000u) : ~(unsigned)ib;
        unsigned long long key =
            ((unsigned long long)u << 32) | (unsigned)__float_as_int(pj.w);
        if (!valid) key = ~0ULL;                  // never inserts
        if (key < heap[KNN_K - 1]) {
            bool c[KNN_K];
#pragma unroll
            for (int s = 0; s < KNN_K; ++s) c[s] = (key < heap[s]);
#pragma unroll
            for (int s = KNN_K - 1; s >= 1; --s)
                heap[s] = c[s - 1] ? heap[s - 1] : (c[s] ? key : heap[s]);
            if (c[0]) heap[0] = key;
            unsigned u15 = (unsigned)(heap[KNN_K - 1] >> 32);
            unsigned fb  = (u15 & 0x80000000u) ? (u15 ^ 0x80000000u) : ~u15;
            worstf = __uint_as_float(fb) + MARGIN;  // NaN while heap unfilled
        }
    };

    process(p, true);                              // self (d = 0)

#pragma unroll 1
    for (int base = 0; base < NPTS; base += 8) {
#pragma unroll
        for (int dd = 1; dd <= 8; ++dd) {
            int d = base + dd;
            process(p - d, (p - d) >= 0);
            process(p + d, (p + d) < NPTS);
        }
        // warp-vote termination: next candidates are at offset base+9
        int nl = p - (base + 9);
        int nr = p + (base + 9);
        float dl = (nl >= 0)   ? (qx - pts[nl].x) : INF;
        float dr = (nr < NPTS) ? (pts[nr].x - qx) : INF;
        float dmin = fminf(dl, dr);
        if (__all_sync(0xFFFFFFFFu, dmin * dmin > worstf)) break;
    }

    int* outp = g_idx + ((size_t)b * NPTS + qi) * KNN_K;
#pragma unroll
    for (int s = 0; s < KNN_K; ++s)
        outp[s] = (int)(heap[s] & 0xFFFFFFFFu);
}

// ---------------------------------------------------------------------------
// Kernel 2: fused MLP chain + pooling + final layer + L2 normalize
// (byte-identical to rounds 3/4)
// ---------------------------------------------------------------------------
struct __align__(16) SmemMLP {
    float2 pts[NPTS];          // 32KB
    float w1[32];              // [8][4]
    float w2[64];              // [8][8]
    float w3[128];             // [16][8]
    float w4[1024];            // [64][16]
    float w5[9216];            // [96][96]
    float mw[64];              // [4][16]
    float mb[4];
    float s1[8],  b1[8];
    float s2[8],  b2[8];
    float s3[16], b3[16];
    float s4[64], b4[64];
    float s5[96], b5[96];
};

extern "C" __global__ void __launch_bounds__(128)
mlp_kernel(const float* __restrict__ x,
           const float* __restrict__ w1, const float* __restrict__ w2,
           const float* __restrict__ w3, const float* __restrict__ w4,
           const float* __restrict__ w5,
           const float* __restrict__ mw, const float* __restrict__ mb,
           const float* __restrict__ bn1, const float* __restrict__ bn2,
           const float* __restrict__ bn3, const float* __restrict__ bn4,
           const float* __restrict__ bn5,
           float* __restrict__ out) {
    extern __shared__ __align__(16) char smem_raw[];
    SmemMLP* sm = (SmemMLP*)smem_raw;

    const int tid = threadIdx.x;
    const int b   = blockIdx.y;

    // cooperative loads
    for (int i = tid; i < NPTS; i += 128) sm->pts[i] = ((const float2*)x)[(size_t)b * NPTS + i];
    for (int i = tid; i < 32;   i += 128) sm->w1[i] = w1[i];
    for (int i = tid; i < 64;   i += 128) sm->w2[i] = w2[i];
    for (int i = tid; i < 128;  i += 128) sm->w3[i] = w3[i];
    for (int i = tid; i < 1024; i += 128) sm->w4[i] = w4[i];
    for (int i = tid; i < 9216; i += 128) sm->w5[i] = w5[i];
    for (int i = tid; i < 64;   i += 128) sm->mw[i] = mw[i];
    if (tid < 4) sm->mb[tid] = mb[tid];
    // fold BN: scale = gamma*rsqrt(var+eps); bias = beta - mean*scale
    for (int i = tid; i < 8;  i += 128) {
        float s = bn1[i] * rsqrtf(bn1[24 + i] + 1e-5f);
        sm->s1[i] = s; sm->b1[i] = bn1[8 + i] - bn1[16 + i] * s;
        float t = bn2[i] * rsqrtf(bn2[24 + i] + 1e-5f);
        sm->s2[i] = t; sm->b2[i] = bn2[8 + i] - bn2[16 + i] * t;
    }
    for (int i = tid; i < 16; i += 128) {
        float s = bn3[i] * rsqrtf(bn3[48 + i] + 1e-5f);
        sm->s3[i] = s; sm->b3[i] = bn3[16 + i] - bn3[32 + i] * s;
    }
    for (int i = tid; i < 64; i += 128) {
        float s = bn4[i] * rsqrtf(bn4[192 + i] + 1e-5f);
        sm->s4[i] = s; sm->b4[i] = bn4[64 + i] - bn4[128 + i] * s;
    }
    for (int i = tid; i < 96; i += 128) {
        float s = bn5[i] * rsqrtf(bn5[288 + i] + 1e-5f);
        sm->s5[i] = s; sm->b5[i] = bn5[96 + i] - bn5[192 + i] * s;
    }
    __syncthreads();

    const int n  = blockIdx.x * 128 + tid;
    const int gq = b * NPTS + n;
    const int* __restrict__ gi = g_idx + (size_t)gq * KNN_K;

    // packed f32x2 pooled-feature accumulators: f[i] holds features (2i, 2i+1)
    unsigned long long f[48];
#pragma unroll
    for (int i = 0; i < 48; ++i) f[i] = 0ULL;

    const float2 ctr = sm->pts[n];

#pragma unroll 1
    for (int k = 0; k < KNN_K; ++k) {
        const int nbk = gi[k];
        const float2 P = sm->pts[nbk];
        const unsigned long long m1p = pack2(sm->mw[k],      sm->mw[k]);
        const unsigned long long m2p = pack2(sm->mw[16 + k], sm->mw[16 + k]);
        const unsigned long long m3p = pack2(sm->mw[32 + k], sm->mw[32 + k]);
        const unsigned long long m4p = pack2(sm->mw[48 + k], sm->mw[48 + k]);

        // layer 1: 4 -> 8
        float h1[8];
#pragma unroll
        for (int o = 0; o < 8; o += 2) {
#pragma unroll
            for (int t = 0; t < 2; ++t) {
                float4 w = *(const float4*)(sm->w1 + (o + t) * 4);
                float v = P.x * w.x + P.y * w.y + ctr.x * w.z + ctr.y * w.w;
                h1[o + t] = fmaxf(fmaf(v, sm->s1[o + t], sm->b1[o + t]), 0.0f);
            }
            f[o / 2] = ffma2(pack2(h1[o], h1[o + 1]), m1p, f[o / 2]);
        }
        // layer 2: 8 -> 8
        float h2[8];
#pragma unroll
        for (int o = 0; o < 8; o += 2) {
#pragma unroll
            for (int t = 0; t < 2; ++t) {
                const float4* w = (const float4*)(sm->w2 + (o + t) * 8);
                float4 wa = w[0], wb = w[1];
                float v = h1[0] * wa.x + h1[1] * wa.y + h1[2] * wa.z + h1[3] * wa.w
                        + h1[4] * wb.x + h1[5] * wb.y + h1[6] * wb.z + h1[7] * wb.w;
                h2[o + t] = fmaxf(fmaf(v, sm->s2[o + t], sm->b2[o + t]), 0.0f);
            }
            f[4 + o / 2] = ffma2(pack2(h2[o], h2[o + 1]), m2p, f[4 + o / 2]);
        }
        // layer 3: 8 -> 16, stored packed in pairs for layer-4 f32x2 dots
        unsigned long long h3p[8];
#pragma unroll
        for (int o = 0; o < 16; o += 2) {
            float vv[2];
#pragma unroll
            for (int t = 0; t < 2; ++t) {
                const float4* w = (const float4*)(sm->w3 + (o + t) * 8);
                float4 wa = w[0], wb = w[1];
                float v = h2[0] * wa.x + h2[1] * wa.y + h2[2] * wa.z + h2[3] * wa.w
                        + h2[4] * wb.x + h2[5] * wb.y + h2[6] * wb.z + h2[7] * wb.w;
                vv[t] = fmaxf(fmaf(v, sm->s3[o + t], sm->b3[o + t]), 0.0f);
            }
            h3p[o / 2] = pack2(vv[0], vv[1]);
            f[8 + o / 2] = ffma2(h3p[o / 2], m3p, f[8 + o / 2]);
        }
        // layer 4: 16 -> 64 (packed f32x2 dot16)
#pragma unroll 1
        for (int o = 0; o < 64; o += 2) {
            float vv[2];
#pragma unroll
            for (int t = 0; t < 2; ++t) {
                const ulonglong2* wrow = (const ulonglong2*)(sm->w4 + (o + t) * 16);
                ulonglong2 wa = wrow[0], wb = wrow[1], wc = wrow[2], wd = wrow[3];
                unsigned long long acc = ffma2(h3p[0], wa.x, 0ULL);
                acc = ffma2(h3p[1], wa.y, acc);
                acc = ffma2(h3p[2], wb.x, acc);
                acc = ffma2(h3p[3], wb.y, acc);
                acc = ffma2(h3p[4], wc.x, acc);
                acc = ffma2(h3p[5], wc.y, acc);
                acc = ffma2(h3p[6], wd.x, acc);
                acc = ffma2(h3p[7], wd.y, acc);
                float lo, hi; unpack2(acc, lo, hi);
                float v = lo + hi;
                vv[t] = fmaxf(fmaf(v, sm->s4[o + t], sm->b4[o + t]), 0.0f);
            }
            f[16 + o / 2] = ffma2(pack2(vv[0], vv[1]), m4p, f[16 + o / 2]);
        }
    }

    // mlp biases (per segment scalar, pair-aligned segments)
    {
        const unsigned long long c0 = pack2(sm->mb[0], sm->mb[0]);
        const unsigned long long c1 = pack2(sm->mb[1], sm->mb[1]);
        const unsigned long long c2 = pack2(sm->mb[2], sm->mb[2]);
        const unsigned long long c3 = pack2(sm->mb[3], sm->mb[3]);
#pragma unroll
        for (int i = 0; i < 4; ++i)  f[i]      = add2(f[i], c0);
#pragma unroll
        for (int i = 0; i < 4; ++i)  f[4 + i]  = add2(f[4 + i], c1);
#pragma unroll
        for (int i = 0; i < 8; ++i)  f[8 + i]  = add2(f[8 + i], c2);
#pragma unroll
        for (int i = 0; i < 32; ++i) f[16 + i] = add2(f[16 + i], c3);
    }

    // final 96x96 layer: 2 outputs per body, 4 independent ffma2 chains
    float* __restrict__ outp = out + (size_t)gq * 96;
    float ss = 0.0f;
#pragma unroll 1
    for (int o = 0; o < 96; o += 2) {
        const ulonglong2* wA = (const ulonglong2*)(sm->w5 + o * 96);
        const ulonglong2* wB = (const ulonglong2*)(sm->w5 + (o + 1) * 96);
        unsigned long long a0 = 0ULL, a1 = 0ULL, b0 = 0ULL, b1 = 0ULL;
#pragma unroll 6
        for (int j = 0; j < 24; ++j) {
            ulonglong2 wa = wA[j];
            ulonglong2 wb = wB[j];
            a0 = ffma2(f[2 * j],     wa.x, a0);
            a1 = ffma2(f[2 * j + 1], wa.y, a1);
            b0 = ffma2(f[2 * j],     wb.x, b0);
            b1 = ffma2(f[2 * j + 1], wb.y, b1);
        }
        unsigned long long accA = add2(a0, a1);
        unsigned long long accB = add2(b0, b1);
        float lo, hi;
        unpack2(accA, lo, hi);
        float vA = lo + hi;
        unpack2(accB, lo, hi);
        float vB = lo + hi;
        vA = fmaxf(fmaf(vA, sm->s5[o],     sm->b5[o]),     0.0f);
        vB = fmaxf(fmaf(vB, sm->s5[o + 1], sm->b5[o + 1]), 0.0f);
        ss = fmaf(vA, vA, ss);
        ss = fmaf(vB, vB, ss);
        outp[o]     = vA;
        outp[o + 1] = vB;
    }

    const float rn = rsqrtf(ss);
    float4* o4 = (float4*)outp;
#pragma unroll 4
    for (int i = 0; i < 24; ++i) {
        float4 v = o4[i];
        v.x *= rn; v.y *= rn; v.z *= rn; v.w *= rn;
        o4[i] = v;
    }
}

// ---------------------------------------------------------------------------
// launch
// ---------------------------------------------------------------------------
extern "C" void kernel_launch(void* const* d_in, const int* in_sizes, int n_in,
                              void* d_out, int out_size) {
    const float* x   = (const float*)d_in[0];
    const float* w1  = (const float*)d_in[1];
    const float* w2  = (const float*)d_in[2];
    const float* w3  = (const float*)d_in[3];
    const float* w4  = (const float*)d_in[4];
    const float* w5  = (const float*)d_in[5];
    const float* mw  = (const float*)d_in[6];
    const float* mb  = (const float*)d_in[7];
    const float* bn1 = (const float*)d_in[8];
    const float* bn2 = (const float*)d_in[9];
    const float* bn3 = (const float*)d_in[10];
    const float* bn4 = (const float*)d_in[11];
    const float* bn5 = (const float*)d_in[12];

    const size_t sort_smem = NPTS * sizeof(unsigned long long);      // 32KB
    const size_t knn_smem  = NPTS * sizeof(float4);                  // 64KB
    const size_t mlp_smem  = sizeof(SmemMLP);                        // ~75KB

    cudaFuncSetAttribute(sort_kernel, cudaFuncAttributeMaxDynamicSharedMemorySize, (int)sort_smem);
    cudaFuncSetAttribute(knn_kernel,  cudaFuncAttributeMaxDynamicSharedMemorySize, (int)knn_smem);
    cudaFuncSetAttribute(mlp_kernel,  cudaFuncAttributeMaxDynamicSharedMemorySize, (int)mlp_smem);

    dim3 grid(NPTS / 128, BATCH);
    sort_kernel<<<BATCH, 1024, sort_smem>>>(x);
    knn_kernel<<<grid, 128, knn_smem>>>();
    mlp_kernel<<<grid, 128, mlp_smem>>>(x, w1, w2, w3, w4, w5, mw, mb,
                                        bn1, bn2, bn3, bn4, bn5, (float*)d_out);
}

// round 6
// speedup vs baseline: 1.4986x; 1.1708x over previous
#include <cuda_runtime.h>
#include <cstdint>

#define NPTS  4096
#define BATCH 8
#define KNN_K 16

// scratch: neighbor indices (original within-batch indices), 2MB
__device__ int g_idx[BATCH * NPTS * KNN_K];
// scratch: pooled features, 96 floats per point packed as 48 u64, 12.6MB
__device__ __align__(16) unsigned long long g_feat[BATCH * NPTS * 48];

// ---------------------------------------------------------------------------
// packed f32x2 helpers
// ---------------------------------------------------------------------------
__device__ __forceinline__ unsigned long long ffma2(unsigned long long a,
                                                    unsigned long long b,
                                                    unsigned long long c) {
    unsigned long long d;
    asm("fma.rn.f32x2 %0, %1, %2, %3;" : "=l"(d) : "l"(a), "l"(b), "l"(c));
    return d;
}
__device__ __forceinline__ unsigned long long add2(unsigned long long a,
                                                   unsigned long long b) {
    unsigned long long d;
    asm("add.rn.f32x2 %0, %1, %2;" : "=l"(d) : "l"(a), "l"(b));
    return d;
}
__device__ __forceinline__ unsigned long long pack2(float lo, float hi) {
    unsigned long long p;
    asm("mov.b64 %0, {%1, %2};" : "=l"(p) : "f"(lo), "f"(hi));
    return p;
}
__device__ __forceinline__ void unpack2(unsigned long long p, float& lo, float& hi) {
    asm("mov.b64 {%0, %1}, %2;" : "=f"(lo), "=f"(hi) : "l"(p));
}

// ---------------------------------------------------------------------------
// Kernel 1: brute-force exact KNN, candidate range SPLIT 2 ways per query.
// 2 threads per query (halves of j-range), round-3 u32 cascade inside a half
// (strict < keeps earliest j = smallest idx among ties), then exact merge of
// the two sorted top-16 lists via u64 (dist,idx) keys + bitonic lower-half.
// Result is bit-identical to the round-3 full scan.
// ---------------------------------------------------------------------------
extern "C" __global__ void __launch_bounds__(128)
knn_kernel(const float* __restrict__ x) {
    extern __shared__ __align__(16) char smem_raw[];
    float2* sxy = (float2*)smem_raw;                                   // 32KB
    float*  ssq = (float*)(smem_raw + NPTS * 8);                       // 16KB
    unsigned long long* mbuf =
        (unsigned long long*)(smem_raw + NPTS * 12);                   // 64*17*8

    const int tid = threadIdx.x;
    const int b   = blockIdx.y;
    const float2* __restrict__ xb = ((const float2*)x) + (size_t)b * NPTS;

    for (int i = tid; i < NPTS; i += 128) {
        float2 v = xb[i];
        sxy[i] = v;
        ssq[i] = __fadd_rn(__fmul_rn(v.x, v.x), __fmul_rn(v.y, v.y));
    }
    __syncthreads();

    const int qloc = tid & 63;
    const int half = tid >> 6;                    // warps 0,1 -> half 0; 2,3 -> half 1
    const int q    = blockIdx.x * 64 + qloc;
    const float2 qv = sxy[q];
    const float qx = qv.x, qy = qv.y, qsq = ssq[q];

    unsigned bu[KNN_K];
    int      bi[KNN_K];
#pragma unroll
    for (int s = 0; s < KNN_K; ++s) { bu[s] = 0xFFFFFFFFu; bi[s] = 0; }

    const int jbeg = half * (NPTS / 2);
#pragma unroll 4
    for (int jj = 0; jj < NPTS / 2; ++jj) {
        const int j = jbeg + jj;
        float2 p = sxy[j];
        float ps = ssq[j];
        // exact reference formula, no FMA contraction
        float dot = __fadd_rn(__fmul_rn(qx, p.x), __fmul_rn(qy, p.y));
        float d   = __fsub_rn(__fadd_rn(qsq, ps), __fmul_rn(2.0f, dot));
        int ib = __float_as_int(d);
        unsigned u = (ib >= 0) ? ((unsigned)ib ^ 0x80000000u) : ~(unsigned)ib;
        if (u < bu[KNN_K - 1]) {
            bool c[KNN_K];
#pragma unroll
            for (int s = 0; s < KNN_K; ++s) c[s] = (u < bu[s]);
#pragma unroll
            for (int s = KNN_K - 1; s >= 1; --s) {
                bu[s] = c[s - 1] ? bu[s - 1] : (c[s] ? u : bu[s]);
                bi[s] = c[s - 1] ? bi[s - 1] : (c[s] ? j : bi[s]);
            }
            if (c[0]) { bu[0] = u; bi[0] = j; }
        }
    }

    if (half == 1) {
#pragma unroll
        for (int s = 0; s < KNN_K; ++s)
            mbuf[qloc * 17 + s] = ((unsigned long long)bu[s] << 32) | (unsigned)bi[s];
    }
    __syncthreads();

    if (half == 0) {
        unsigned long long L[KNN_K];
        // lower-half extraction of bitonic merge: L[i] = min(a[i], b[15-i])
#pragma unroll
        for (int i = 0; i < KNN_K; ++i) {
            unsigned long long a =
                ((unsigned long long)bu[i] << 32) | (unsigned)bi[i];
            unsigned long long bb = mbuf[qloc * 17 + (KNN_K - 1 - i)];
            L[i] = (a < bb) ? a : bb;
        }
        // L is bitonic; sort it with stages 8,4,2,1 (static network)
#pragma unroll
        for (int j = 8; j >= 1; j >>= 1) {
#pragma unroll
            for (int i = 0; i < KNN_K; ++i) {
                if ((i & j) == 0) {
                    unsigned long long lo = L[i], hi = L[i | j];
                    unsigned long long mn = (lo < hi) ? lo : hi;
                    unsigned long long mx = (lo < hi) ? hi : lo;
                    L[i] = mn; L[i | j] = mx;
                }
            }
        }
        int* outp = g_idx + ((size_t)b * NPTS + q) * KNN_K;
#pragma unroll
        for (int s = 0; s < KNN_K; ++s)
            outp[s] = (int)(L[s] & 0xFFFFFFFFu);
    }
}

// ---------------------------------------------------------------------------
// Kernel 2a: pooling (layers 1-4 over 16 neighbors), feature-split:
// part 0 -> features [0..48)  (layer1/2/3 pools + layer4 outputs 0..15)
// part 1 -> features [48..96) (layer4 outputs 16..63)
// Both parts recompute the cheap h1/h2/h3 chain. Writes g_feat.
// ---------------------------------------------------------------------------
struct __align__(16) SmemPool {
    float2 pts[NPTS];          // 32KB
    float w1[32];              // [8][4]
    float w2[64];              // [8][8]
    float w3[128];             // [16][8]
    float w4[1024];            // [64][16]
    float mw[64];              // [4][16]
    float mb[4];
    float s1[8],  b1[8];
    float s2[8],  b2[8];
    float s3[16], b3[16];
    float s4[64], b4[64];
};

extern "C" __global__ void __launch_bounds__(128)
pool_kernel(const float* __restrict__ x,
            const float* __restrict__ w1, const float* __restrict__ w2,
            const float* __restrict__ w3, const float* __restrict__ w4,
            const float* __restrict__ mw, const float* __restrict__ mb,
            const float* __restrict__ bn1, const float* __restrict__ bn2,
            const float* __restrict__ bn3, const float* __restrict__ bn4) {
    extern __shared__ __align__(16) char smem_raw[];
    SmemPool* sm = (SmemPool*)smem_raw;

    const int tid = threadIdx.x;
    const int b   = blockIdx.y;

    for (int i = tid; i < NPTS; i += 128) sm->pts[i] = ((const float2*)x)[(size_t)b * NPTS + i];
    for (int i = tid; i < 32;   i += 128) sm->w1[i] = w1[i];
    for (int i = tid; i < 64;   i += 128) sm->w2[i] = w2[i];
    for (int i = tid; i < 128;  i += 128) sm->w3[i] = w3[i];
    for (int i = tid; i < 1024; i += 128) sm->w4[i] = w4[i];
    for (int i = tid; i < 64;   i += 128) sm->mw[i] = mw[i];
    if (tid < 4) sm->mb[tid] = mb[tid];
    for (int i = tid; i < 8;  i += 128) {
        float s = bn1[i] * rsqrtf(bn1[24 + i] + 1e-5f);
        sm->s1[i] = s; sm->b1[i] = bn1[8 + i] - bn1[16 + i] * s;
        float t = bn2[i] * rsqrtf(bn2[24 + i] + 1e-5f);
        sm->s2[i] = t; sm->b2[i] = bn2[8 + i] - bn2[16 + i] * t;
    }
    for (int i = tid; i < 16; i += 128) {
        float s = bn3[i] * rsqrtf(bn3[48 + i] + 1e-5f);
        sm->s3[i] = s; sm->b3[i] = bn3[16 + i] - bn3[32 + i] * s;
    }
    for (int i = tid; i < 64; i += 128) {
        float s = bn4[i] * rsqrtf(bn4[192 + i] + 1e-5f);
        sm->s4[i] = s; sm->b4[i] = bn4[64 + i] - bn4[128 + i] * s;
    }
    __syncthreads();

    const int nloc = tid & 63;
    const int part = tid >> 6;                    // warp-uniform
    const int n    = blockIdx.x * 64 + nloc;
    const int gq   = b * NPTS + n;
    const int* __restrict__ gi = g_idx + (size_t)gq * KNN_K;

    unsigned long long facc[24];
#pragma unroll
    for (int i = 0; i < 24; ++i) facc[i] = 0ULL;

    const float2 ctr = sm->pts[n];
    const int obeg = part ? 16 : 0;
    const int oend = part ? 64 : 16;

#pragma unroll 1
    for (int k = 0; k < KNN_K; ++k) {
        const int nbk = gi[k];
        const float2 P = sm->pts[nbk];
        const unsigned long long m1p = pack2(sm->mw[k],      sm->mw[k]);
        const unsigned long long m2p = pack2(sm->mw[16 + k], sm->mw[16 + k]);
        const unsigned long long m3p = pack2(sm->mw[32 + k], sm->mw[32 + k]);
        const unsigned long long m4p = pack2(sm->mw[48 + k], sm->mw[48 + k]);

        // layer 1: 4 -> 8
        float h1[8];
#pragma unroll
        for (int o = 0; o < 8; o += 2) {
#pragma unroll
            for (int t = 0; t < 2; ++t) {
                float4 w = *(const float4*)(sm->w1 + (o + t) * 4);
                float v = P.x * w.x + P.y * w.y + ctr.x * w.z + ctr.y * w.w;
                h1[o + t] = fmaxf(fmaf(v, sm->s1[o + t], sm->b1[o + t]), 0.0f);
            }
            if (part == 0)
                facc[o / 2] = ffma2(pack2(h1[o], h1[o + 1]), m1p, facc[o / 2]);
        }
        // layer 2: 8 -> 8
        float h2[8];
#pragma unroll
        for (int o = 0; o < 8; o += 2) {
#pragma unroll
            for (int t = 0; t < 2; ++t) {
                const float4* w = (const float4*)(sm->w2 + (o + t) * 8);
                float4 wa = w[0], wb = w[1];
                float v = h1[0] * wa.x + h1[1] * wa.y + h1[2] * wa.z + h1[3] * wa.w
                        + h1[4] * wb.x + h1[5] * wb.y + h1[6] * wb.z + h1[7] * wb.w;
                h2[o + t] = fmaxf(fmaf(v, sm->s2[o + t], sm->b2[o + t]), 0.0f);
            }
            if (part == 0)
                facc[4 + o / 2] = ffma2(pack2(h2[o], h2[o + 1]), m2p, facc[4 + o / 2]);
        }
        // layer 3: 8 -> 16 (packed pairs for layer-4 dots)
        unsigned long long h3p[8];
#pragma unroll
        for (int o = 0; o < 16; o += 2) {
            float vv[2];
#pragma unroll
            for (int t = 0; t < 2; ++t) {
                const float4* w = (const float4*)(sm->w3 + (o + t) * 8);
                float4 wa = w[0], wb = w[1];
                float v = h2[0] * wa.x + h2[1] * wa.y + h2[2] * wa.z + h2[3] * wa.w
                        + h2[4] * wb.x + h2[5] * wb.y + h2[6] * wb.z + h2[7] * wb.w;
                vv[t] = fmaxf(fmaf(v, sm->s3[o + t], sm->b3[o + t]), 0.0f);
            }
            h3p[o / 2] = pack2(vv[0], vv[1]);
            if (part == 0)
                facc[8 + o / 2] = ffma2(h3p[o / 2], m3p, facc[8 + o / 2]);
        }
        // layer 4: this part's output range
#pragma unroll 1
        for (int o = obeg; o < oend; o += 2) {
            float vv[2];
#pragma unroll
            for (int t = 0; t < 2; ++t) {
                const ulonglong2* wrow = (const ulonglong2*)(sm->w4 + (o + t) * 16);
                ulonglong2 wa = wrow[0], wb = wrow[1], wc = wrow[2], wd = wrow[3];
                unsigned long long acc = ffma2(h3p[0], wa.x, 0ULL);
                acc = ffma2(h3p[1], wa.y, acc);
                acc = ffma2(h3p[2], wb.x, acc);
                acc = ffma2(h3p[3], wb.y, acc);
                acc = ffma2(h3p[4], wc.x, acc);
                acc = ffma2(h3p[5], wc.y, acc);
                acc = ffma2(h3p[6], wd.x, acc);
                acc = ffma2(h3p[7], wd.y, acc);
                float lo, hi; unpack2(acc, lo, hi);
                float v = lo + hi;
                vv[t] = fmaxf(fmaf(v, sm->s4[o + t], sm->b4[o + t]), 0.0f);
            }
            const int fi = (part ? (o - 16) : (o + 32)) >> 1;
            facc[fi] = ffma2(pack2(vv[0], vv[1]), m4p, facc[fi]);
        }
    }

    // mlp biases
    {
        const unsigned long long c3 = pack2(sm->mb[3], sm->mb[3]);
        if (part == 0) {
            const unsigned long long c0 = pack2(sm->mb[0], sm->mb[0]);
            const unsigned long long c1 = pack2(sm->mb[1], sm->mb[1]);
            const unsigned long long c2 = pack2(sm->mb[2], sm->mb[2]);
#pragma unroll
            for (int i = 0; i < 4; ++i)  facc[i]      = add2(facc[i], c0);
#pragma unroll
            for (int i = 0; i < 4; ++i)  facc[4 + i]  = add2(facc[4 + i], c1);
#pragma unroll
            for (int i = 0; i < 8; ++i)  facc[8 + i]  = add2(facc[8 + i], c2);
#pragma unroll
            for (int i = 0; i < 8; ++i)  facc[16 + i] = add2(facc[16 + i], c3);
        } else {
#pragma unroll
            for (int i = 0; i < 24; ++i) facc[i] = add2(facc[i], c3);
        }
    }

    ulonglong2* dst = (ulonglong2*)(g_feat + (size_t)gq * 48 + part * 24);
#pragma unroll
    for (int i = 0; i < 12; ++i)
        dst[i] = make_ulonglong2(facc[2 * i], facc[2 * i + 1]);
}

// ---------------------------------------------------------------------------
// Kernel 2b: final 96x96 GEMM + BN/ReLU + L2 normalize.
// 2 threads per point, k-split (f halves) combined via shfl_xor(1).
// Unnormalized v stored to out, then rescaled by this thread (own half only).
// ---------------------------------------------------------------------------
struct __align__(16) SmemGemm {
    float w5[9216];            // [96][96]
    float s5[96], b5[96];
};

extern "C" __global__ void __launch_bounds__(128)
gemm_kernel(const float* __restrict__ w5, const float* __restrict__ bn5,
            float* __restrict__ out) {
    extern __shared__ __align__(16) char smem_raw[];
    SmemGemm* sm = (SmemGemm*)smem_raw;

    const int tid = threadIdx.x;
    const int b   = blockIdx.y;

    for (int i = tid; i < 9216; i += 128) sm->w5[i] = w5[i];
    for (int i = tid; i < 96; i += 128) {
        float s = bn5[i] * rsqrtf(bn5[288 + i] + 1e-5f);
        sm->s5[i] = s; sm->b5[i] = bn5[96 + i] - bn5[192 + i] * s;
    }
    __syncthreads();

    const int half = tid & 1;
    const int n    = blockIdx.x * 64 + (tid >> 1);
    const int gq   = b * NPTS + n;

    // load this half's 48 features (24 u64)
    unsigned long long fh[24];
    const ulonglong2* fsrc = (const ulonglong2*)(g_feat + (size_t)gq * 48 + half * 24);
#pragma unroll
    for (int i = 0; i < 12; ++i) {
        ulonglong2 t = fsrc[i];
        fh[2 * i] = t.x; fh[2 * i + 1] = t.y;
    }

    const int obase = half * 48;
    float* __restrict__ mybase = out + (size_t)gq * 96 + obase;
    float ss = 0.0f;

#pragma unroll 1
    for (int o = 0; o < 96; ++o) {
        const ulonglong2* wrow = (const ulonglong2*)(sm->w5 + o * 96 + half * 48);
        unsigned long long a0 = 0ULL, a1 = 0ULL;
#pragma unroll
        for (int j = 0; j < 12; ++j) {
            ulonglong2 w = wrow[j];
            a0 = ffma2(fh[2 * j],     w.x, a0);
            a1 = ffma2(fh[2 * j + 1], w.y, a1);
        }
        float lo, hi; unpack2(add2(a0, a1), lo, hi);
        float ph = lo + hi;
        float full = ph + __shfl_xor_sync(0xFFFFFFFFu, ph, 1);
        float v = fmaxf(fmaf(full, sm->s5[o], sm->b5[o]), 0.0f);
        ss = fmaf(v, v, ss);
        const int rel = o - obase;
        if ((unsigned)rel < 48u) mybase[rel] = v;   // unnormalized, own half
    }

    const float rn = rsqrtf(ss);
    float4* o4 = (float4*)mybase;
#pragma unroll 3
    for (int i = 0; i < 12; ++i) {
        float4 v = o4[i];
        v.x *= rn; v.y *= rn; v.z *= rn; v.w *= rn;
        o4[i] = v;
    }
}

// ---------------------------------------------------------------------------
// launch
// ---------------------------------------------------------------------------
extern "C" void kernel_launch(void* const* d_in, const int* in_sizes, int n_in,
                              void* d_out, int out_size) {
    const float* x   = (const float*)d_in[0];
    const float* w1  = (const float*)d_in[1];
    const float* w2  = (const float*)d_in[2];
    const float* w3  = (const float*)d_in[3];
    const float* w4  = (const float*)d_in[4];
    const float* w5  = (const float*)d_in[5];
    const float* mw  = (const float*)d_in[6];
    const float* mb  = (const float*)d_in[7];
    const float* bn1 = (const float*)d_in[8];
    const float* bn2 = (const float*)d_in[9];
    const float* bn3 = (const float*)d_in[10];
    const float* bn4 = (const float*)d_in[11];
    const float* bn5 = (const float*)d_in[12];

    const size_t knn_smem  = NPTS * 12 + 64 * 17 * 8;     // ~57.9KB
    const size_t pool_smem = sizeof(SmemPool);            // ~38.8KB
    const size_t gemm_smem = sizeof(SmemGemm);            // ~37.6KB

    cudaFuncSetAttribute(knn_kernel,  cudaFuncAttributeMaxDynamicSharedMemorySize, (int)knn_smem);
    cudaFuncSetAttribute(pool_kernel, cudaFuncAttributeMaxDynamicSharedMemorySize, (int)pool_smem);
    cudaFuncSetAttribute(gemm_kernel, cudaFuncAttributeMaxDynamicSharedMemorySize, (int)gemm_smem);

    dim3 grid(NPTS / 64, BATCH);   // 64 x 8 = 512 blocks, 128 threads each
    knn_kernel<<<grid, 128, knn_smem>>>(x);
    pool_kernel<<<grid, 128, pool_smem>>>(x, w1, w2, w3, w4, mw, mb,
                                          bn1, bn2, bn3, bn4);
    gemm_kernel<<<grid, 128, gemm_smem>>>(w5, bn5, (float*)d_out);
}

// round 7
// speedup vs baseline: 1.9539x; 1.3038x over previous
#include <cuda_runtime.h>
#include <cstdint>

#define NPTS  4096
#define BATCH 8
#define KNN_K 16

// scratch: neighbor indices (original within-batch indices), 2MB
__device__ int g_idx[BATCH * NPTS * KNN_K];
// scratch: pooled features, 96 floats per point packed as 48 u64, 12.6MB
__device__ __align__(16) unsigned long long g_feat[BATCH * NPTS * 48];

// ---------------------------------------------------------------------------
// packed f32x2 helpers
// ---------------------------------------------------------------------------
__device__ __forceinline__ unsigned long long ffma2(unsigned long long a,
                                                    unsigned long long b,
                                                    unsigned long long c) {
    unsigned long long d;
    asm("fma.rn.f32x2 %0, %1, %2, %3;" : "=l"(d) : "l"(a), "l"(b), "l"(c));
    return d;
}
__device__ __forceinline__ unsigned long long add2(unsigned long long a,
                                                   unsigned long long b) {
    unsigned long long d;
    asm("add.rn.f32x2 %0, %1, %2;" : "=l"(d) : "l"(a), "l"(b));
    return d;
}
__device__ __forceinline__ unsigned long long pack2(float lo, float hi) {
    unsigned long long p;
    asm("mov.b64 %0, {%1, %2};" : "=l"(p) : "f"(lo), "f"(hi));
    return p;
}
__device__ __forceinline__ void unpack2(unsigned long long p, float& lo, float& hi) {
    asm("mov.b64 {%0, %1}, %2;" : "=f"(lo), "=f"(hi) : "l"(p));
}

// ---------------------------------------------------------------------------
// Kernel 1: exact KNN, 2 threads/query (half ranges), buffered top-16.
// Hot loop: distance + threshold test + predicated FIFO push (NO cascade).
// Cascade runs only in drains (ballot-gated), re-checked against the
// current threshold. Push order preserves j order -> tie handling identical
// to the round-6 cascade (strict <, earliest j wins among equal dists).
// Merge of the two halves identical to round 6 (validated).
// ---------------------------------------------------------------------------
#define QCAP 16   // per-lane FIFO capacity (u64 entries)

extern "C" __global__ void __launch_bounds__(128)
knn_kernel(const float* __restrict__ x) {
    extern __shared__ __align__(16) char smem_raw[];
    float2* sxy = (float2*)smem_raw;                                   // 32KB
    float*  ssq = (float*)(smem_raw + NPTS * 8);                       // 16KB
    unsigned long long* mbuf =
        (unsigned long long*)(smem_raw + NPTS * 12);                   // 64*17*8
    unsigned long long* qbuf = mbuf + 64 * 17;                         // 16KB

    const int tid = threadIdx.x;
    const int b   = blockIdx.y;
    const float2* __restrict__ xb = ((const float2*)x) + (size_t)b * NPTS;

    for (int i = tid; i < NPTS; i += 128) {
        float2 v = xb[i];
        sxy[i] = v;
        ssq[i] = __fadd_rn(__fmul_rn(v.x, v.x), __fmul_rn(v.y, v.y));
    }
    __syncthreads();

    const int qloc = tid & 63;
    const int half = tid >> 6;                    // warps 0,1 -> half 0; 2,3 -> half 1
    const int q    = blockIdx.x * 64 + qloc;
    const float2 qv = sxy[q];
    const float qx = qv.x, qy = qv.y, qsq = ssq[q];

    unsigned bu[KNN_K];
    int      bi[KNN_K];
#pragma unroll
    for (int s = 0; s < KNN_K; ++s) { bu[s] = 0xFFFFFFFFu; bi[s] = 0; }

    const int jbeg = half * (NPTS / 2);
    int cnt = 0;

    // full cascade insert (identical to round 6)
    auto insert = [&](unsigned u, int j) {
        bool c[KNN_K];
#pragma unroll
        for (int s = 0; s < KNN_K; ++s) c[s] = (u < bu[s]);
#pragma unroll
        for (int s = KNN_K - 1; s >= 1; --s) {
            bu[s] = c[s - 1] ? bu[s - 1] : (c[s] ? u : bu[s]);
            bi[s] = c[s - 1] ? bi[s - 1] : (c[s] ? j : bi[s]);
        }
        if (c[0]) { bu[0] = u; bi[0] = j; }
    };

    auto drain = [&]() {
#pragma unroll 1
        for (int t = 0; t < cnt; ++t) {           // divergent per-lane count
            unsigned long long key = qbuf[t * 128 + tid];
            unsigned u = (unsigned)(key >> 32);
            if (u < bu[KNN_K - 1]) insert(u, (int)(key & 0xFFFFFFFFu));
        }
        cnt = 0;
    };

#pragma unroll 1
    for (int blk = 0; blk < NPTS / 2; blk += 8) {
#pragma unroll
        for (int s = 0; s < 8; ++s) {
            const int j = jbeg + blk + s;
            float2 p = sxy[j];
            float ps = ssq[j];
            // exact reference formula, no FMA contraction
            float dot = __fadd_rn(__fmul_rn(qx, p.x), __fmul_rn(qy, p.y));
            float d   = __fsub_rn(__fadd_rn(qsq, ps), __fmul_rn(2.0f, dot));
            int ib = __float_as_int(d);
            unsigned u = (ib >= 0) ? ((unsigned)ib ^ 0x80000000u) : ~(unsigned)ib;
            if (u < bu[KNN_K - 1]) {              // tiny body -> predicated
                qbuf[cnt * 128 + tid] =
                    ((unsigned long long)u << 32) | (unsigned)j;
                ++cnt;
            }
        }
        if (__any_sync(0xFFFFFFFFu, cnt >= QCAP - 8)) drain();
    }
    drain();                                      // leftovers

    if (half == 1) {
#pragma unroll
        for (int s = 0; s < KNN_K; ++s)
            mbuf[qloc * 17 + s] = ((unsigned long long)bu[s] << 32) | (unsigned)bi[s];
    }
    __syncthreads();

    if (half == 0) {
        unsigned long long L[KNN_K];
        // lower-half extraction of bitonic merge: L[i] = min(a[i], b[15-i])
#pragma unroll
        for (int i = 0; i < KNN_K; ++i) {
            unsigned long long a =
                ((unsigned long long)bu[i] << 32) | (unsigned)bi[i];
            unsigned long long bb = mbuf[qloc * 17 + (KNN_K - 1 - i)];
            L[i] = (a < bb) ? a : bb;
        }
        // L is bitonic; sort with stages 8,4,2,1 (static network)
#pragma unroll
        for (int j = 8; j >= 1; j >>= 1) {
#pragma unroll
            for (int i = 0; i < KNN_K; ++i) {
                if ((i & j) == 0) {
                    unsigned long long lo = L[i], hi = L[i | j];
                    unsigned long long mn = (lo < hi) ? lo : hi;
                    unsigned long long mx = (lo < hi) ? hi : lo;
                    L[i] = mn; L[i | j] = mx;
                }
            }
        }
        int* outp = g_idx + ((size_t)b * NPTS + q) * KNN_K;
#pragma unroll
        for (int s = 0; s < KNN_K; ++s)
            outp[s] = (int)(L[s] & 0xFFFFFFFFu);
    }
}

// ---------------------------------------------------------------------------
// Kernel 2a: pooling (layers 1-4 over 16 neighbors), feature-split
// (byte-identical to round 6)
// ---------------------------------------------------------------------------
struct __align__(16) SmemPool {
    float2 pts[NPTS];          // 32KB
    float w1[32];              // [8][4]
    float w2[64];              // [8][8]
    float w3[128];             // [16][8]
    float w4[1024];            // [64][16]
    float mw[64];              // [4][16]
    float mb[4];
    float s1[8],  b1[8];
    float s2[8],  b2[8];
    float s3[16], b3[16];
    float s4[64], b4[64];
};

extern "C" __global__ void __launch_bounds__(128)
pool_kernel(const float* __restrict__ x,
            const float* __restrict__ w1, const float* __restrict__ w2,
            const float* __restrict__ w3, const float* __restrict__ w4,
            const float* __restrict__ mw, const float* __restrict__ mb,
            const float* __restrict__ bn1, const float* __restrict__ bn2,
            const float* __restrict__ bn3, const float* __restrict__ bn4) {
    extern __shared__ __align__(16) char smem_raw[];
    SmemPool* sm = (SmemPool*)smem_raw;

    const int tid = threadIdx.x;
    const int b   = blockIdx.y;

    for (int i = tid; i < NPTS; i += 128) sm->pts[i] = ((const float2*)x)[(size_t)b * NPTS + i];
    for (int i = tid; i < 32;   i += 128) sm->w1[i] = w1[i];
    for (int i = tid; i < 64;   i += 128) sm->w2[i] = w2[i];
    for (int i = tid; i < 128;  i += 128) sm->w3[i] = w3[i];
    for (int i = tid; i < 1024; i += 128) sm->w4[i] = w4[i];
    for (int i = tid; i < 64;   i += 128) sm->mw[i] = mw[i];
    if (tid < 4) sm->mb[tid] = mb[tid];
    for (int i = tid; i < 8;  i += 128) {
        float s = bn1[i] * rsqrtf(bn1[24 + i] + 1e-5f);
        sm->s1[i] = s; sm->b1[i] = bn1[8 + i] - bn1[16 + i] * s;
        float t = bn2[i] * rsqrtf(bn2[24 + i] + 1e-5f);
        sm->s2[i] = t; sm->b2[i] = bn2[8 + i] - bn2[16 + i] * t;
    }
    for (int i = tid; i < 16; i += 128) {
        float s = bn3[i] * rsqrtf(bn3[48 + i] + 1e-5f);
        sm->s3[i] = s; sm->b3[i] = bn3[16 + i] - bn3[32 + i] * s;
    }
    for (int i = tid; i < 64; i += 128) {
        float s = bn4[i] * rsqrtf(bn4[192 + i] + 1e-5f);
        sm->s4[i] = s; sm->b4[i] = bn4[64 + i] - bn4[128 + i] * s;
    }
    __syncthreads();

    const int nloc = tid & 63;
    const int part = tid >> 6;                    // warp-uniform
    const int n    = blockIdx.x * 64 + nloc;
    const int gq   = b * NPTS + n;
    const int* __restrict__ gi = g_idx + (size_t)gq * KNN_K;

    unsigned long long facc[24];
#pragma unroll
    for (int i = 0; i < 24; ++i) facc[i] = 0ULL;

    const float2 ctr = sm->pts[n];
    const int obeg = part ? 16 : 0;
    const int oend = part ? 64 : 16;

#pragma unroll 1
    for (int k = 0; k < KNN_K; ++k) {
        const int nbk = gi[k];
        const float2 P = sm->pts[nbk];
        const unsigned long long m1p = pack2(sm->mw[k],      sm->mw[k]);
        const unsigned long long m2p = pack2(sm->mw[16 + k], sm->mw[16 + k]);
        const unsigned long long m3p = pack2(sm->mw[32 + k], sm->mw[32 + k]);
        const unsigned long long m4p = pack2(sm->mw[48 + k], sm->mw[48 + k]);

        // layer 1: 4 -> 8
        float h1[8];
#pragma unroll
        for (int o = 0; o < 8; o += 2) {
#pragma unroll
            for (int t = 0; t < 2; ++t) {
                float4 w = *(const float4*)(sm->w1 + (o + t) * 4);
                float v = P.x * w.x + P.y * w.y + ctr.x * w.z + ctr.y * w.w;
                h1[o + t] = fmaxf(fmaf(v, sm->s1[o + t], sm->b1[o + t]), 0.0f);
            }
            if (part == 0)
                facc[o / 2] = ffma2(pack2(h1[o], h1[o + 1]), m1p, facc[o / 2]);
        }
        // layer 2: 8 -> 8
        float h2[8];
#pragma unroll
        for (int o = 0; o < 8; o += 2) {
#pragma unroll
            for (int t = 0; t < 2; ++t) {
                const float4* w = (const float4*)(sm->w2 + (o + t) * 8);
                float4 wa = w[0], wb = w[1];
                float v = h1[0] * wa.x + h1[1] * wa.y + h1[2] * wa.z + h1[3] * wa.w
                        + h1[4] * wb.x + h1[5] * wb.y + h1[6] * wb.z + h1[7] * wb.w;
                h2[o + t] = fmaxf(fmaf(v, sm->s2[o + t], sm->b2[o + t]), 0.0f);
            }
            if (part == 0)
                facc[4 + o / 2] = ffma2(pack2(h2[o], h2[o + 1]), m2p, facc[4 + o / 2]);
        }
        // layer 3: 8 -> 16 (packed pairs for layer-4 dots)
        unsigned long long h3p[8];
#pragma unroll
        for (int o = 0; o < 16; o += 2) {
            float vv[2];
#pragma unroll
            for (int t = 0; t < 2; ++t) {
                const float4* w = (const float4*)(sm->w3 + (o + t) * 8);
                float4 wa = w[0], wb = w[1];
                float v = h2[0] * wa.x + h2[1] * wa.y + h2[2] * wa.z + h2[3] * wa.w
                        + h2[4] * wb.x + h2[5] * wb.y + h2[6] * wb.z + h2[7] * wb.w;
                vv[t] = fmaxf(fmaf(v, sm->s3[o + t], sm->b3[o + t]), 0.0f);
            }
            h3p[o / 2] = pack2(vv[0], vv[1]);
            if (part == 0)
                facc[8 + o / 2] = ffma2(h3p[o / 2], m3p, facc[8 + o / 2]);
        }
        // layer 4: this part's output range
#pragma unroll 1
        for (int o = obeg; o < oend; o += 2) {
            float vv[2];
#pragma unroll
            for (int t = 0; t < 2; ++t) {
                const ulonglong2* wrow = (const ulonglong2*)(sm->w4 + (o + t) * 16);
                ulonglong2 wa = wrow[0], wb = wrow[1], wc = wrow[2], wd = wrow[3];
                unsigned long long acc = ffma2(h3p[0], wa.x, 0ULL);
                acc = ffma2(h3p[1], wa.y, acc);
                acc = ffma2(h3p[2], wb.x, acc);
                acc = ffma2(h3p[3], wb.y, acc);
                acc = ffma2(h3p[4], wc.x, acc);
                acc = ffma2(h3p[5], wc.y, acc);
                acc = ffma2(h3p[6], wd.x, acc);
                acc = ffma2(h3p[7], wd.y, acc);
                float lo, hi; unpack2(acc, lo, hi);
                float v = lo + hi;
                vv[t] = fmaxf(fmaf(v, sm->s4[o + t], sm->b4[o + t]), 0.0f);
            }
            const int fi = (part ? (o - 16) : (o + 32)) >> 1;
            facc[fi] = ffma2(pack2(vv[0], vv[1]), m4p, facc[fi]);
        }
    }

    // mlp biases
    {
        const unsigned long long c3 = pack2(sm->mb[3], sm->mb[3]);
        if (part == 0) {
            const unsigned long long c0 = pack2(sm->mb[0], sm->mb[0]);
            const unsigned long long c1 = pack2(sm->mb[1], sm->mb[1]);
            const unsigned long long c2 = pack2(sm->mb[2], sm->mb[2]);
#pragma unroll
            for (int i = 0; i < 4; ++i)  facc[i]      = add2(facc[i], c0);
#pragma unroll
            for (int i = 0; i < 4; ++i)  facc[4 + i]  = add2(facc[4 + i], c1);
#pragma unroll
            for (int i = 0; i < 8; ++i)  facc[8 + i]  = add2(facc[8 + i], c2);
#pragma unroll
            for (int i = 0; i < 8; ++i)  facc[16 + i] = add2(facc[16 + i], c3);
        } else {
#pragma unroll
            for (int i = 0; i < 24; ++i) facc[i] = add2(facc[i], c3);
        }
    }

    ulonglong2* dst = (ulonglong2*)(g_feat + (size_t)gq * 48 + part * 24);
#pragma unroll
    for (int i = 0; i < 12; ++i)
        dst[i] = make_ulonglong2(facc[2 * i], facc[2 * i + 1]);
}

// ---------------------------------------------------------------------------
// Kernel 2b: final 96x96 GEMM + BN/ReLU + L2 normalize
// (byte-identical to round 6)
// ---------------------------------------------------------------------------
struct __align__(16) SmemGemm {
    float w5[9216];            // [96][96]
    float s5[96], b5[96];
};

extern "C" __global__ void __launch_bounds__(128)
gemm_kernel(const float* __restrict__ w5, const float* __restrict__ bn5,
            float* __restrict__ out) {
    extern __shared__ __align__(16) char smem_raw[];
    SmemGemm* sm = (SmemGemm*)smem_raw;

    const int tid = threadIdx.x;
    const int b   = blockIdx.y;

    for (int i = tid; i < 9216; i += 128) sm->w5[i] = w5[i];
    for (int i = tid; i < 96; i += 128) {
        float s = bn5[i] * rsqrtf(bn5[288 + i] + 1e-5f);
        sm->s5[i] = s; sm->b5[i] = bn5[96 + i] - bn5[192 + i] * s;
    }
    __syncthreads();

    const int half = tid & 1;
    const int n    = blockIdx.x * 64 + (tid >> 1);
    const int gq   = b * NPTS + n;

    unsigned long long fh[24];
    const ulonglong2* fsrc = (const ulonglong2*)(g_feat + (size_t)gq * 48 + half * 24);
#pragma unroll
    for (int i = 0; i < 12; ++i) {
        ulonglong2 t = fsrc[i];
        fh[2 * i] = t.x; fh[2 * i + 1] = t.y;
    }

    const int obase = half * 48;
    float* __restrict__ mybase = out + (size_t)gq * 96 + obase;
    float ss = 0.0f;

#pragma unroll 1
    for (int o = 0; o < 96; ++o) {
        const ulonglong2* wrow = (const ulonglong2*)(sm->w5 + o * 96 + half * 48);
        unsigned long long a0 = 0ULL, a1 = 0ULL;
#pragma unroll
        for (int j = 0; j < 12; ++j) {
            ulonglong2 w = wrow[j];
            a0 = ffma2(fh[2 * j],     w.x, a0);
            a1 = ffma2(fh[2 * j + 1], w.y, a1);
        }
        float lo, hi; unpack2(add2(a0, a1), lo, hi);
        float ph = lo + hi;
        float full = ph + __shfl_xor_sync(0xFFFFFFFFu, ph, 1);
        float v = fmaxf(fmaf(full, sm->s5[o], sm->b5[o]), 0.0f);
        ss = fmaf(v, v, ss);
        const int rel = o - obase;
        if ((unsigned)rel < 48u) mybase[rel] = v;   // unnormalized, own half
    }

    const float rn = rsqrtf(ss);
    float4* o4 = (float4*)mybase;
#pragma unroll 3
    for (int i = 0; i < 12; ++i) {
        float4 v = o4[i];
        v.x *= rn; v.y *= rn; v.z *= rn; v.w *= rn;
        o4[i] = v;
    }
}

// ---------------------------------------------------------------------------
// launch
// ---------------------------------------------------------------------------
extern "C" void kernel_launch(void* const* d_in, const int* in_sizes, int n_in,
                              void* d_out, int out_size) {
    const float* x   = (const float*)d_in[0];
    const float* w1  = (const float*)d_in[1];
    const float* w2  = (const float*)d_in[2];
    const float* w3  = (const float*)d_in[3];
    const float* w4  = (const float*)d_in[4];
    const float* w5  = (const float*)d_in[5];
    const float* mw  = (const float*)d_in[6];
    const float* mb  = (const float*)d_in[7];
    const float* bn1 = (const float*)d_in[8];
    const float* bn2 = (const float*)d_in[9];
    const float* bn3 = (const float*)d_in[10];
    const float* bn4 = (const float*)d_in[11];
    const float* bn5 = (const float*)d_in[12];

    const size_t knn_smem  = NPTS * 12 + 64 * 17 * 8 + 128 * QCAP * 8;  // ~73.5KB
    const size_t pool_smem = sizeof(SmemPool);            // ~38.8KB
    const size_t gemm_smem = sizeof(SmemGemm);            // ~37.6KB

    cudaFuncSetAttribute(knn_kernel,  cudaFuncAttributeMaxDynamicSharedMemorySize, (int)knn_smem);
    cudaFuncSetAttribute(pool_kernel, cudaFuncAttributeMaxDynamicSharedMemorySize, (int)pool_smem);
    cudaFuncSetAttribute(gemm_kernel, cudaFuncAttributeMaxDynamicSharedMemorySize, (int)gemm_smem);

    dim3 grid(NPTS / 64, BATCH);   // 64 x 8 = 512 blocks, 128 threads each
    knn_kernel<<<grid, 128, knn_smem>>>(x);
    pool_kernel<<<grid, 128, pool_smem>>>(x, w1, w2, w3, w4, mw, mb,
                                          bn1, bn2, bn3, bn4);
    gemm_kernel<<<grid, 128, gemm_smem>>>(w5, bn5, (float*)d_out);
}

// round 8
// speedup vs baseline: 2.2547x; 1.1540x over previous
#include <cuda_runtime.h>
#include <cstdint>

#define NPTS  4096
#define BATCH 8
#define KNN_K 16

// scratch: neighbor indices (original within-batch indices), 2MB
__device__ int g_idx[BATCH * NPTS * KNN_K];
// scratch: pooled features, 96 floats per point packed as 48 u64, 12.6MB
__device__ __align__(16) unsigned long long g_feat[BATCH * NPTS * 48];

// ---------------------------------------------------------------------------
// packed f32x2 helpers
// ---------------------------------------------------------------------------
__device__ __forceinline__ unsigned long long ffma2(unsigned long long a,
                                                    unsigned long long b,
                                                    unsigned long long c) {
    unsigned long long d;
    asm("fma.rn.f32x2 %0, %1, %2, %3;" : "=l"(d) : "l"(a), "l"(b), "l"(c));
    return d;
}
__device__ __forceinline__ unsigned long long add2(unsigned long long a,
                                                   unsigned long long b) {
    unsigned long long d;
    asm("add.rn.f32x2 %0, %1, %2;" : "=l"(d) : "l"(a), "l"(b));
    return d;
}
__device__ __forceinline__ unsigned long long pack2(float lo, float hi) {
    unsigned long long p;
    asm("mov.b64 %0, {%1, %2};" : "=l"(p) : "f"(lo), "f"(hi));
    return p;
}
__device__ __forceinline__ void unpack2(unsigned long long p, float& lo, float& hi) {
    asm("mov.b64 {%0, %1}, %2;" : "=f"(lo), "=f"(hi) : "l"(p));
}

// sorted u64 lower-half bitonic merge: a (sorted asc) x b (sorted asc) -> a
__device__ __forceinline__ void merge16(unsigned long long* a,
                                        const unsigned long long* bsrc) {
    unsigned long long L[KNN_K];
#pragma unroll
    for (int i = 0; i < KNN_K; ++i) {
        unsigned long long bb = bsrc[KNN_K - 1 - i];
        L[i] = (a[i] < bb) ? a[i] : bb;
    }
#pragma unroll
    for (int j = 8; j >= 1; j >>= 1) {
#pragma unroll
        for (int i = 0; i < KNN_K; ++i) {
            if ((i & j) == 0) {
                unsigned long long lo = L[i], hi = L[i | j];
                unsigned long long mn = (lo < hi) ? lo : hi;
                unsigned long long mx = (lo < hi) ? hi : lo;
                L[i] = mn; L[i | j] = mx;
            }
        }
    }
#pragma unroll
    for (int i = 0; i < KNN_K; ++i) a[i] = L[i];
}

// ---------------------------------------------------------------------------
// Kernel 1: exact KNN, 4 threads/query (quarter ranges), buffered top-16.
// Hot loop: distance + threshold test + predicated FIFO push (no cascade).
// Cascade runs only in ballot-gated drains. Quarters are ascending-j and the
// within-quarter cascade uses strict < (earliest j wins ties), so merging the
// 4 sorted lists by u64 (dist,idx) keys reproduces the full-scan result.
// ---------------------------------------------------------------------------
#define QCAP 16   // per-lane FIFO capacity (u64 entries)

extern "C" __global__ void __launch_bounds__(256)
knn_kernel(const float* __restrict__ x) {
    extern __shared__ __align__(16) char smem_raw[];
    float2* sxy = (float2*)smem_raw;                                   // 32KB
    float*  ssq = (float*)(smem_raw + NPTS * 8);                       // 16KB
    unsigned long long* mbuf =
        (unsigned long long*)(smem_raw + NPTS * 12);                   // 3*64*17*8
    unsigned long long* qbuf = mbuf + 3 * 64 * 17;                     // 32KB

    const int tid = threadIdx.x;
    const int b   = blockIdx.y;
    const float2* __restrict__ xb = ((const float2*)x) + (size_t)b * NPTS;

    for (int i = tid; i < NPTS; i += 256) {
        float2 v = xb[i];
        sxy[i] = v;
        ssq[i] = __fadd_rn(__fmul_rn(v.x, v.x), __fmul_rn(v.y, v.y));
    }
    __syncthreads();

    const int qloc = tid & 63;
    const int part = tid >> 6;                    // warp-uniform (2 warps/part)
    const int q    = blockIdx.x * 64 + qloc;
    const float2 qv = sxy[q];
    const float qx = qv.x, qy = qv.y, qsq = ssq[q];

    unsigned bu[KNN_K];
    int      bi[KNN_K];
#pragma unroll
    for (int s = 0; s < KNN_K; ++s) { bu[s] = 0xFFFFFFFFu; bi[s] = 0; }

    const int jbeg = part * (NPTS / 4);
    int cnt = 0;

    auto insert = [&](unsigned u, int j) {
        bool c[KNN_K];
#pragma unroll
        for (int s = 0; s < KNN_K; ++s) c[s] = (u < bu[s]);
#pragma unroll
        for (int s = KNN_K - 1; s >= 1; --s) {
            bu[s] = c[s - 1] ? bu[s - 1] : (c[s] ? u : bu[s]);
            bi[s] = c[s - 1] ? bi[s - 1] : (c[s] ? j : bi[s]);
        }
        if (c[0]) { bu[0] = u; bi[0] = j; }
    };

    auto drain = [&]() {
#pragma unroll 1
        for (int t = 0; t < cnt; ++t) {           // divergent per-lane count
            unsigned long long key = qbuf[t * 256 + tid];
            unsigned u = (unsigned)(key >> 32);
            if (u < bu[KNN_K - 1]) insert(u, (int)(key & 0xFFFFFFFFu));
        }
        cnt = 0;
    };

#pragma unroll 1
    for (int blk = 0; blk < NPTS / 4; blk += 8) {
#pragma unroll
        for (int s = 0; s < 8; ++s) {
            const int j = jbeg + blk + s;
            float2 p = sxy[j];
            float ps = ssq[j];
            // exact reference formula, no FMA contraction
            float dot = __fadd_rn(__fmul_rn(qx, p.x), __fmul_rn(qy, p.y));
            float d   = __fsub_rn(__fadd_rn(qsq, ps), __fmul_rn(2.0f, dot));
            int ib = __float_as_int(d);
            unsigned u = (ib >= 0) ? ((unsigned)ib ^ 0x80000000u) : ~(unsigned)ib;
            if (u < bu[KNN_K - 1]) {              // tiny body -> predicated
                qbuf[cnt * 256 + tid] =
                    ((unsigned long long)u << 32) | (unsigned)j;
                ++cnt;
            }
        }
        if (__any_sync(0xFFFFFFFFu, cnt >= QCAP - 8)) drain();
    }
    drain();                                      // leftovers

    // parts 1..3 publish their sorted lists
    if (part != 0) {
        unsigned long long* dst = mbuf + ((part - 1) * 64 + qloc) * 17;
#pragma unroll
        for (int s = 0; s < KNN_K; ++s)
            dst[s] = ((unsigned long long)bu[s] << 32) | (unsigned)bi[s];
    }
    __syncthreads();

    if (part == 0) {
        unsigned long long L[KNN_K];
#pragma unroll
        for (int s = 0; s < KNN_K; ++s)
            L[s] = ((unsigned long long)bu[s] << 32) | (unsigned)bi[s];

        // merge part1 into L
        merge16(L, mbuf + (0 * 64 + qloc) * 17);
        // merge parts 2,3 together, then into L
        unsigned long long M[KNN_K];
        const unsigned long long* p2 = mbuf + (1 * 64 + qloc) * 17;
#pragma unroll
        for (int s = 0; s < KNN_K; ++s) M[s] = p2[s];
        merge16(M, mbuf + (2 * 64 + qloc) * 17);
        merge16(L, M);

        int* outp = g_idx + ((size_t)b * NPTS + q) * KNN_K;
#pragma unroll
        for (int s = 0; s < KNN_K; ++s)
            outp[s] = (int)(L[s] & 0xFFFFFFFFu);
    }
}

// ---------------------------------------------------------------------------
// Kernel 2a: pooling (layers 1-4 over 16 neighbors), feature-split
// (byte-identical to rounds 6/7)
// ---------------------------------------------------------------------------
struct __align__(16) SmemPool {
    float2 pts[NPTS];          // 32KB
    float w1[32];              // [8][4]
    float w2[64];              // [8][8]
    float w3[128];             // [16][8]
    float w4[1024];            // [64][16]
    float mw[64];              // [4][16]
    float mb[4];
    float s1[8],  b1[8];
    float s2[8],  b2[8];
    float s3[16], b3[16];
    float s4[64], b4[64];
};

extern "C" __global__ void __launch_bounds__(128)
pool_kernel(const float* __restrict__ x,
            const float* __restrict__ w1, const float* __restrict__ w2,
            const float* __restrict__ w3, const float* __restrict__ w4,
            const float* __restrict__ mw, const float* __restrict__ mb,
            const float* __restrict__ bn1, const float* __restrict__ bn2,
            const float* __restrict__ bn3, const float* __restrict__ bn4) {
    extern __shared__ __align__(16) char smem_raw[];
    SmemPool* sm = (SmemPool*)smem_raw;

    const int tid = threadIdx.x;
    const int b   = blockIdx.y;

    for (int i = tid; i < NPTS; i += 128) sm->pts[i] = ((const float2*)x)[(size_t)b * NPTS + i];
    for (int i = tid; i < 32;   i += 128) sm->w1[i] = w1[i];
    for (int i = tid; i < 64;   i += 128) sm->w2[i] = w2[i];
    for (int i = tid; i < 128;  i += 128) sm->w3[i] = w3[i];
    for (int i = tid; i < 1024; i += 128) sm->w4[i] = w4[i];
    for (int i = tid; i < 64;   i += 128) sm->mw[i] = mw[i];
    if (tid < 4) sm->mb[tid] = mb[tid];
    for (int i = tid; i < 8;  i += 128) {
        float s = bn1[i] * rsqrtf(bn1[24 + i] + 1e-5f);
        sm->s1[i] = s; sm->b1[i] = bn1[8 + i] - bn1[16 + i] * s;
        float t = bn2[i] * rsqrtf(bn2[24 + i] + 1e-5f);
        sm->s2[i] = t; sm->b2[i] = bn2[8 + i] - bn2[16 + i] * t;
    }
    for (int i = tid; i < 16; i += 128) {
        float s = bn3[i] * rsqrtf(bn3[48 + i] + 1e-5f);
        sm->s3[i] = s; sm->b3[i] = bn3[16 + i] - bn3[32 + i] * s;
    }
    for (int i = tid; i < 64; i += 128) {
        float s = bn4[i] * rsqrtf(bn4[192 + i] + 1e-5f);
        sm->s4[i] = s; sm->b4[i] = bn4[64 + i] - bn4[128 + i] * s;
    }
    __syncthreads();

    const int nloc = tid & 63;
    const int part = tid >> 6;                    // warp-uniform
    const int n    = blockIdx.x * 64 + nloc;
    const int gq   = b * NPTS + n;
    const int* __restrict__ gi = g_idx + (size_t)gq * KNN_K;

    unsigned long long facc[24];
#pragma unroll
    for (int i = 0; i < 24; ++i) facc[i] = 0ULL;

    const float2 ctr = sm->pts[n];
    const int obeg = part ? 16 : 0;
    const int oend = part ? 64 : 16;

#pragma unroll 1
    for (int k = 0; k < KNN_K; ++k) {
        const int nbk = gi[k];
        const float2 P = sm->pts[nbk];
        const unsigned long long m1p = pack2(sm->mw[k],      sm->mw[k]);
        const unsigned long long m2p = pack2(sm->mw[16 + k], sm->mw[16 + k]);
        const unsigned long long m3p = pack2(sm->mw[32 + k], sm->mw[32 + k]);
        const unsigned long long m4p = pack2(sm->mw[48 + k], sm->mw[48 + k]);

        // layer 1: 4 -> 8
        float h1[8];
#pragma unroll
        for (int o = 0; o < 8; o += 2) {
#pragma unroll
            for (int t = 0; t < 2; ++t) {
                float4 w = *(const float4*)(sm->w1 + (o + t) * 4);
                float v = P.x * w.x + P.y * w.y + ctr.x * w.z + ctr.y * w.w;
                h1[o + t] = fmaxf(fmaf(v, sm->s1[o + t], sm->b1[o + t]), 0.0f);
            }
            if (part == 0)
                facc[o / 2] = ffma2(pack2(h1[o], h1[o + 1]), m1p, facc[o / 2]);
        }
        // layer 2: 8 -> 8
        float h2[8];
#pragma unroll
        for (int o = 0; o < 8; o += 2) {
#pragma unroll
            for (int t = 0; t < 2; ++t) {
                const float4* w = (const float4*)(sm->w2 + (o + t) * 8);
                float4 wa = w[0], wb = w[1];
                float v = h1[0] * wa.x + h1[1] * wa.y + h1[2] * wa.z + h1[3] * wa.w
                        + h1[4] * wb.x + h1[5] * wb.y + h1[6] * wb.z + h1[7] * wb.w;
                h2[o + t] = fmaxf(fmaf(v, sm->s2[o + t], sm->b2[o + t]), 0.0f);
            }
            if (part == 0)
                facc[4 + o / 2] = ffma2(pack2(h2[o], h2[o + 1]), m2p, facc[4 + o / 2]);
        }
        // layer 3: 8 -> 16 (packed pairs for layer-4 dots)
        unsigned long long h3p[8];
#pragma unroll
        for (int o = 0; o < 16; o += 2) {
            float vv[2];
#pragma unroll
            for (int t = 0; t < 2; ++t) {
                const float4* w = (const float4*)(sm->w3 + (o + t) * 8);
                float4 wa = w[0], wb = w[1];
                float v = h2[0] * wa.x + h2[1] * wa.y + h2[2] * wa.z + h2[3] * wa.w
                        + h2[4] * wb.x + h2[5] * wb.y + h2[6] * wb.z + h2[7] * wb.w;
                vv[t] = fmaxf(fmaf(v, sm->s3[o + t], sm->b3[o + t]), 0.0f);
            }
            h3p[o / 2] = pack2(vv[0], vv[1]);
            if (part == 0)
                facc[8 + o / 2] = ffma2(h3p[o / 2], m3p, facc[8 + o / 2]);
        }
        // layer 4: this part's output range
#pragma unroll 1
        for (int o = obeg; o < oend; o += 2) {
            float vv[2];
#pragma unroll
            for (int t = 0; t < 2; ++t) {
                const ulonglong2* wrow = (const ulonglong2*)(sm->w4 + (o + t) * 16);
                ulonglong2 wa = wrow[0], wb = wrow[1], wc = wrow[2], wd = wrow[3];
                unsigned long long acc = ffma2(h3p[0], wa.x, 0ULL);
                acc = ffma2(h3p[1], wa.y, acc);
                acc = ffma2(h3p[2], wb.x, acc);
                acc = ffma2(h3p[3], wb.y, acc);
                acc = ffma2(h3p[4], wc.x, acc);
                acc = ffma2(h3p[5], wc.y, acc);
                acc = ffma2(h3p[6], wd.x, acc);
                acc = ffma2(h3p[7], wd.y, acc);
                float lo, hi; unpack2(acc, lo, hi);
                float v = lo + hi;
                vv[t] = fmaxf(fmaf(v, sm->s4[o + t], sm->b4[o + t]), 0.0f);
            }
            const int fi = (part ? (o - 16) : (o + 32)) >> 1;
            facc[fi] = ffma2(pack2(vv[0], vv[1]), m4p, facc[fi]);
        }
    }

    // mlp biases
    {
        const unsigned long long c3 = pack2(sm->mb[3], sm->mb[3]);
        if (part == 0) {
            const unsigned long long c0 = pack2(sm->mb[0], sm->mb[0]);
            const unsigned long long c1 = pack2(sm->mb[1], sm->mb[1]);
            const unsigned long long c2 = pack2(sm->mb[2], sm->mb[2]);
#pragma unroll
            for (int i = 0; i < 4; ++i)  facc[i]      = add2(facc[i], c0);
#pragma unroll
            for (int i = 0; i < 4; ++i)  facc[4 + i]  = add2(facc[4 + i], c1);
#pragma unroll
            for (int i = 0; i < 8; ++i)  facc[8 + i]  = add2(facc[8 + i], c2);
#pragma unroll
            for (int i = 0; i < 8; ++i)  facc[16 + i] = add2(facc[16 + i], c3);
        } else {
#pragma unroll
            for (int i = 0; i < 24; ++i) facc[i] = add2(facc[i], c3);
        }
    }

    ulonglong2* dst = (ulonglong2*)(g_feat + (size_t)gq * 48 + part * 24);
#pragma unroll
    for (int i = 0; i < 12; ++i)
        dst[i] = make_ulonglong2(facc[2 * i], facc[2 * i + 1]);
}

// ---------------------------------------------------------------------------
// Kernel 2b: final 96x96 GEMM + BN/ReLU + L2 normalize
// (byte-identical to rounds 6/7)
// ---------------------------------------------------------------------------
struct __align__(16) SmemGemm {
    float w5[9216];            // [96][96]
    float s5[96], b5[96];
};

extern "C" __global__ void __launch_bounds__(128)
gemm_kernel(const float* __restrict__ w5, const float* __restrict__ bn5,
            float* __restrict__ out) {
    extern __shared__ __align__(16) char smem_raw[];
    SmemGemm* sm = (SmemGemm*)smem_raw;

    const int tid = threadIdx.x;
    const int b   = blockIdx.y;

    for (int i = tid; i < 9216; i += 128) sm->w5[i] = w5[i];
    for (int i = tid; i < 96; i += 128) {
        float s = bn5[i] * rsqrtf(bn5[288 + i] + 1e-5f);
        sm->s5[i] = s; sm->b5[i] = bn5[96 + i] - bn5[192 + i] * s;
    }
    __syncthreads();

    const int half = tid & 1;
    const int n    = blockIdx.x * 64 + (tid >> 1);
    const int gq   = b * NPTS + n;

    unsigned long long fh[24];
    const ulonglong2* fsrc = (const ulonglong2*)(g_feat + (size_t)gq * 48 + half * 24);
#pragma unroll
    for (int i = 0; i < 12; ++i) {
        ulonglong2 t = fsrc[i];
        fh[2 * i] = t.x; fh[2 * i + 1] = t.y;
    }

    const int obase = half * 48;
    float* __restrict__ mybase = out + (size_t)gq * 96 + obase;
    float ss = 0.0f;

#pragma unroll 1
    for (int o = 0; o < 96; ++o) {
        const ulonglong2* wrow = (const ulonglong2*)(sm->w5 + o * 96 + half * 48);
        unsigned long long a0 = 0ULL, a1 = 0ULL;
#pragma unroll
        for (int j = 0; j < 12; ++j) {
            ulonglong2 w = wrow[j];
            a0 = ffma2(fh[2 * j],     w.x, a0);
            a1 = ffma2(fh[2 * j + 1], w.y, a1);
        }
        float lo, hi; unpack2(add2(a0, a1), lo, hi);
        float ph = lo + hi;
        float full = ph + __shfl_xor_sync(0xFFFFFFFFu, ph, 1);
        float v = fmaxf(fmaf(full, sm->s5[o], sm->b5[o]), 0.0f);
        ss = fmaf(v, v, ss);
        const int rel = o - obase;
        if ((unsigned)rel < 48u) mybase[rel] = v;   // unnormalized, own half
    }

    const float rn = rsqrtf(ss);
    float4* o4 = (float4*)mybase;
#pragma unroll 3
    for (int i = 0; i < 12; ++i) {
        float4 v = o4[i];
        v.x *= rn; v.y *= rn; v.z *= rn; v.w *= rn;
        o4[i] = v;
    }
}

// ---------------------------------------------------------------------------
// launch
// ---------------------------------------------------------------------------
extern "C" void kernel_launch(void* const* d_in, const int* in_sizes, int n_in,
                              void* d_out, int out_size) {
    const float* x   = (const float*)d_in[0];
    const float* w1  = (const float*)d_in[1];
    const float* w2  = (const float*)d_in[2];
    const float* w3  = (const float*)d_in[3];
    const float* w4  = (const float*)d_in[4];
    const float* w5  = (const float*)d_in[5];
    const float* mw  = (const float*)d_in[6];
    const float* mb  = (const float*)d_in[7];
    const float* bn1 = (const float*)d_in[8];
    const float* bn2 = (const float*)d_in[9];
    const float* bn3 = (const float*)d_in[10];
    const float* bn4 = (const float*)d_in[11];
    const float* bn5 = (const float*)d_in[12];

    const size_t knn_smem  = NPTS * 12 + 3 * 64 * 17 * 8 + 256 * QCAP * 8; // ~106KB
    const size_t pool_smem = sizeof(SmemPool);            // ~38.8KB
    const size_t gemm_smem = sizeof(SmemGemm);            // ~37.6KB

    cudaFuncSetAttribute(knn_kernel,  cudaFuncAttributeMaxDynamicSharedMemorySize, (int)knn_smem);
    cudaFuncSetAttribute(pool_kernel, cudaFuncAttributeMaxDynamicSharedMemorySize, (int)pool_smem);
    cudaFuncSetAttribute(gemm_kernel, cudaFuncAttributeMaxDynamicSharedMemorySize, (int)gemm_smem);

    dim3 grid(NPTS / 64, BATCH);   // 64 x 8 = 512 blocks
    knn_kernel<<<grid, 256, knn_smem>>>(x);
    pool_kernel<<<grid, 128, pool_smem>>>(x, w1, w2, w3, w4, mw, mb,
                                          bn1, bn2, bn3, bn4);
    gemm_kernel<<<grid, 128, gemm_smem>>>(w5, bn5, (float*)d_out);
}

// round 9
// speedup vs baseline: 2.4854x; 1.1023x over previous
#include <cuda_runtime.h>
#include <cstdint>

#define NPTS  4096
#define BATCH 8
#define KNN_K 16

// scratch: neighbor indices (original within-batch indices), 2MB
__device__ int g_idx[BATCH * NPTS * KNN_K];
// scratch: pooled features, 96 floats per point packed as 48 u64, 12.6MB
__device__ __align__(16) unsigned long long g_feat[BATCH * NPTS * 48];

// ---------------------------------------------------------------------------
// packed f32x2 helpers
// ---------------------------------------------------------------------------
__device__ __forceinline__ unsigned long long ffma2(unsigned long long a,
                                                    unsigned long long b,
                                                    unsigned long long c) {
    unsigned long long d;
    asm("fma.rn.f32x2 %0, %1, %2, %3;" : "=l"(d) : "l"(a), "l"(b), "l"(c));
    return d;
}
__device__ __forceinline__ unsigned long long add2(unsigned long long a,
                                                   unsigned long long b) {
    unsigned long long d;
    asm("add.rn.f32x2 %0, %1, %2;" : "=l"(d) : "l"(a), "l"(b));
    return d;
}
__device__ __forceinline__ unsigned long long mul2(unsigned long long a,
                                                   unsigned long long b) {
    unsigned long long d;
    asm("mul.rn.f32x2 %0, %1, %2;" : "=l"(d) : "l"(a), "l"(b));
    return d;
}
__device__ __forceinline__ unsigned long long pack2(float lo, float hi) {
    unsigned long long p;
    asm("mov.b64 %0, {%1, %2};" : "=l"(p) : "f"(lo), "f"(hi));
    return p;
}
__device__ __forceinline__ void unpack2(unsigned long long p, float& lo, float& hi) {
    asm("mov.b64 {%0, %1}, %2;" : "=f"(lo), "=f"(hi) : "l"(p));
}

// sorted u64 lower-half bitonic merge: a (sorted asc) x b (sorted asc) -> a
__device__ __forceinline__ void merge16(unsigned long long* a,
                                        const unsigned long long* bsrc) {
    unsigned long long L[KNN_K];
#pragma unroll
    for (int i = 0; i < KNN_K; ++i) {
        unsigned long long bb = bsrc[KNN_K - 1 - i];
        L[i] = (a[i] < bb) ? a[i] : bb;
    }
#pragma unroll
    for (int j = 8; j >= 1; j >>= 1) {
#pragma unroll
        for (int i = 0; i < KNN_K; ++i) {
            if ((i & j) == 0) {
                unsigned long long lo = L[i], hi = L[i | j];
                unsigned long long mn = (lo < hi) ? lo : hi;
                unsigned long long mx = (lo < hi) ? hi : lo;
                L[i] = mn; L[i | j] = mx;
            }
        }
    }
#pragma unroll
    for (int i = 0; i < KNN_K; ++i) a[i] = L[i];
}

// ---------------------------------------------------------------------------
// Kernel 1: exact KNN, 4 threads/query (quarter ranges), buffered top-16.
// Hot loop: PACKED f32x2 distance for 2 candidates/iter (bit-exact per-half
// RN identical to the scalar reference formula), float threshold test,
// predicated u32 FIFO push (index only). Drains recompute the distance with
// the exact scalar formula and re-check with the bit-exact u-compare, then
// run the validated cascade. Merge of 4 sorted lists identical to round 8.
// ---------------------------------------------------------------------------
#define QCAP 16   // per-lane FIFO capacity (u32 entries)

extern "C" __global__ void __launch_bounds__(256)
knn_kernel(const float* __restrict__ x) {
    extern __shared__ __align__(16) char smem_raw[];
    float2* sxy = (float2*)smem_raw;                                   // 32KB
    float*  ssq = (float*)(smem_raw + NPTS * 8);                       // 16KB
    unsigned long long* mbuf =
        (unsigned long long*)(smem_raw + NPTS * 12);                   // 3*64*17*8
    unsigned* qbuf = (unsigned*)(mbuf + 3 * 64 * 17);                  // 16KB

    const int tid = threadIdx.x;
    const int b   = blockIdx.y;
    const float2* __restrict__ xb = ((const float2*)x) + (size_t)b * NPTS;

    for (int i = tid; i < NPTS; i += 256) {
        float2 v = xb[i];
        sxy[i] = v;
        ssq[i] = __fadd_rn(__fmul_rn(v.x, v.x), __fmul_rn(v.y, v.y));
    }
    __syncthreads();

    const int qloc = tid & 63;
    const int part = tid >> 6;                    // warp-uniform (2 warps/part)
    const int q    = blockIdx.x * 64 + qloc;
    const float2 qv = sxy[q];
    const float qx = qv.x, qy = qv.y, qsq = ssq[q];

    // sentinel = mapped(+INF); unmaps to float +INF for the threshold
    unsigned bu[KNN_K];
    int      bi[KNN_K];
#pragma unroll
    for (int s = 0; s < KNN_K; ++s) { bu[s] = 0xFF800000u; bi[s] = 0; }

    const int jbeg = part * (NPTS / 4);
    int cnt = 0;
    float worstf = __int_as_float(0x7F800000);    // +INF

    auto insert = [&](unsigned u, int j) {
        bool c[KNN_K];
#pragma unroll
        for (int s = 0; s < KNN_K; ++s) c[s] = (u < bu[s]);
#pragma unroll
        for (int s = KNN_K - 1; s >= 1; --s) {
            bu[s] = c[s - 1] ? bu[s - 1] : (c[s] ? u : bu[s]);
            bi[s] = c[s - 1] ? bi[s - 1] : (c[s] ? j : bi[s]);
        }
        if (c[0]) { bu[0] = u; bi[0] = j; }
    };

    auto drain = [&]() {
#pragma unroll 1
        for (int t = 0; t < cnt; ++t) {           // divergent per-lane count
            int j = (int)qbuf[t * 256 + tid];
            float2 p = sxy[j];
            float ps = ssq[j];
            // exact reference formula, no FMA contraction
            float dot = __fadd_rn(__fmul_rn(qx, p.x), __fmul_rn(qy, p.y));
            float d   = __fsub_rn(__fadd_rn(qsq, ps), __fmul_rn(2.0f, dot));
            int ib = __float_as_int(d);
            unsigned u = (ib >= 0) ? ((unsigned)ib ^ 0x80000000u) : ~(unsigned)ib;
            if (u < bu[KNN_K - 1]) insert(u, j);
        }
        cnt = 0;
        // unmap bu[15] -> float threshold (sentinel -> +INF)
        unsigned u15 = bu[KNN_K - 1];
        int ib = (u15 & 0x80000000u) ? (int)(u15 ^ 0x80000000u) : (int)~u15;
        worstf = __int_as_float(ib);
    };

    const unsigned long long qx2 = pack2(qx, qx);
    const unsigned long long qy2 = pack2(qy, qy);
    const unsigned long long qs2 = pack2(qsq, qsq);
    const unsigned long long n22 = pack2(-2.0f, -2.0f);

#pragma unroll 1
    for (int blk = 0; blk < NPTS / 4; blk += 8) {
#pragma unroll
        for (int pp = 0; pp < 4; ++pp) {
            const int j = jbeg + blk + pp * 2;
            float4 pxy = *(const float4*)(sxy + j);        // x0,y0,x1,y1
            float2 ps  = *(const float2*)(ssq + j);
            unsigned long long px  = pack2(pxy.x, pxy.z);
            unsigned long long py  = pack2(pxy.y, pxy.w);
            unsigned long long psq = pack2(ps.x, ps.y);
            // per-half identical rounding to the scalar reference:
            // dot = fadd(fmul(qx,px), fmul(qy,py))
            // d   = fadd(fadd(qsq,ps), fmul(-2,dot))  ==  fsub(fadd(qsq,ps), fmul(2,dot))
            unsigned long long dot = add2(mul2(qx2, px), mul2(qy2, py));
            unsigned long long dv  = add2(add2(qs2, psq), mul2(n22, dot));
            float d0, d1; unpack2(dv, d0, d1);
            if (d0 < worstf) { qbuf[cnt * 256 + tid] = (unsigned)j;       ++cnt; }
            if (d1 < worstf) { qbuf[cnt * 256 + tid] = (unsigned)(j + 1); ++cnt; }
        }
        if (__any_sync(0xFFFFFFFFu, cnt >= QCAP - 8)) drain();
    }
    drain();                                      // leftovers

    // parts 1..3 publish their sorted lists
    if (part != 0) {
        unsigned long long* dst = mbuf + ((part - 1) * 64 + qloc) * 17;
#pragma unroll
        for (int s = 0; s < KNN_K; ++s)
            dst[s] = ((unsigned long long)bu[s] << 32) | (unsigned)bi[s];
    }
    __syncthreads();

    if (part == 0) {
        unsigned long long L[KNN_K];
#pragma unroll
        for (int s = 0; s < KNN_K; ++s)
            L[s] = ((unsigned long long)bu[s] << 32) | (unsigned)bi[s];

        merge16(L, mbuf + (0 * 64 + qloc) * 17);
        unsigned long long M[KNN_K];
        const unsigned long long* p2 = mbuf + (1 * 64 + qloc) * 17;
#pragma unroll
        for (int s = 0; s < KNN_K; ++s) M[s] = p2[s];
        merge16(M, mbuf + (2 * 64 + qloc) * 17);
        merge16(L, M);

        int* outp = g_idx + ((size_t)b * NPTS + q) * KNN_K;
#pragma unroll
        for (int s = 0; s < KNN_K; ++s)
            outp[s] = (int)(L[s] & 0xFFFFFFFFu);
    }
}

// ---------------------------------------------------------------------------
// Kernel 2a: pooling (layers 1-4 over 16 neighbors), feature-split
// (byte-identical to rounds 6/7/8)
// ---------------------------------------------------------------------------
struct __align__(16) SmemPool {
    float2 pts[NPTS];          // 32KB
    float w1[32];              // [8][4]
    float w2[64];              // [8][8]
    float w3[128];             // [16][8]
    float w4[1024];            // [64][16]
    float mw[64];              // [4][16]
    float mb[4];
    float s1[8],  b1[8];
    float s2[8],  b2[8];
    float s3[16], b3[16];
    float s4[64], b4[64];
};

extern "C" __global__ void __launch_bounds__(128)
pool_kernel(const float* __restrict__ x,
            const float* __restrict__ w1, const float* __restrict__ w2,
            const float* __restrict__ w3, const float* __restrict__ w4,
            const float* __restrict__ mw, const float* __restrict__ mb,
            const float* __restrict__ bn1, const float* __restrict__ bn2,
            const float* __restrict__ bn3, const float* __restrict__ bn4) {
    extern __shared__ __align__(16) char smem_raw[];
    SmemPool* sm = (SmemPool*)smem_raw;

    const int tid = threadIdx.x;
    const int b   = blockIdx.y;

    for (int i = tid; i < NPTS; i += 128) sm->pts[i] = ((const float2*)x)[(size_t)b * NPTS + i];
    for (int i = tid; i < 32;   i += 128) sm->w1[i] = w1[i];
    for (int i = tid; i < 64;   i += 128) sm->w2[i] = w2[i];
    for (int i = tid; i < 128;  i += 128) sm->w3[i] = w3[i];
    for (int i = tid; i < 1024; i += 128) sm->w4[i] = w4[i];
    for (int i = tid; i < 64;   i += 128) sm->mw[i] = mw[i];
    if (tid < 4) sm->mb[tid] = mb[tid];
    for (int i = tid; i < 8;  i += 128) {
        float s = bn1[i] * rsqrtf(bn1[24 + i] + 1e-5f);
        sm->s1[i] = s; sm->b1[i] = bn1[8 + i] - bn1[16 + i] * s;
        float t = bn2[i] * rsqrtf(bn2[24 + i] + 1e-5f);
        sm->s2[i] = t; sm->b2[i] = bn2[8 + i] - bn2[16 + i] * t;
    }
    for (int i = tid; i < 16; i += 128) {
        float s = bn3[i] * rsqrtf(bn3[48 + i] + 1e-5f);
        sm->s3[i] = s; sm->b3[i] = bn3[16 + i] - bn3[32 + i] * s;
    }
    for (int i = tid; i < 64; i += 128) {
        float s = bn4[i] * rsqrtf(bn4[192 + i] + 1e-5f);
        sm->s4[i] = s; sm->b4[i] = bn4[64 + i] - bn4[128 + i] * s;
    }
    __syncthreads();

    const int nloc = tid & 63;
    const int part = tid >> 6;                    // warp-uniform
    const int n    = blockIdx.x * 64 + nloc;
    const int gq   = b * NPTS + n;
    const int* __restrict__ gi = g_idx + (size_t)gq * KNN_K;

    unsigned long long facc[24];
#pragma unroll
    for (int i = 0; i < 24; ++i) facc[i] = 0ULL;

    const float2 ctr = sm->pts[n];
    const int obeg = part ? 16 : 0;
    const int oend = part ? 64 : 16;

#pragma unroll 1
    for (int k = 0; k < KNN_K; ++k) {
        const int nbk = gi[k];
        const float2 P = sm->pts[nbk];
        const unsigned long long m1p = pack2(sm->mw[k],      sm->mw[k]);
        const unsigned long long m2p = pack2(sm->mw[16 + k], sm->mw[16 + k]);
        const unsigned long long m3p = pack2(sm->mw[32 + k], sm->mw[32 + k]);
        const unsigned long long m4p = pack2(sm->mw[48 + k], sm->mw[48 + k]);

        // layer 1: 4 -> 8
        float h1[8];
#pragma unroll
        for (int o = 0; o < 8; o += 2) {
#pragma unroll
            for (int t = 0; t < 2; ++t) {
                float4 w = *(const float4*)(sm->w1 + (o + t) * 4);
                float v = P.x * w.x + P.y * w.y + ctr.x * w.z + ctr.y * w.w;
                h1[o + t] = fmaxf(fmaf(v, sm->s1[o + t], sm->b1[o + t]), 0.0f);
            }
            if (part == 0)
                facc[o / 2] = ffma2(pack2(h1[o], h1[o + 1]), m1p, facc[o / 2]);
        }
        // layer 2: 8 -> 8
        float h2[8];
#pragma unroll
        for (int o = 0; o < 8; o += 2) {
#pragma unroll
            for (int t = 0; t < 2; ++t) {
                const float4* w = (const float4*)(sm->w2 + (o + t) * 8);
                float4 wa = w[0], wb = w[1];
                float v = h1[0] * wa.x + h1[1] * wa.y + h1[2] * wa.z + h1[3] * wa.w
                        + h1[4] * wb.x + h1[5] * wb.y + h1[6] * wb.z + h1[7] * wb.w;
                h2[o + t] = fmaxf(fmaf(v, sm->s2[o + t], sm->b2[o + t]), 0.0f);
            }
            if (part == 0)
                facc[4 + o / 2] = ffma2(pack2(h2[o], h2[o + 1]), m2p, facc[4 + o / 2]);
        }
        // layer 3: 8 -> 16 (packed pairs for layer-4 dots)
        unsigned long long h3p[8];
#pragma unroll
        for (int o = 0; o < 16; o += 2) {
            float vv[2];
#pragma unroll
            for (int t = 0; t < 2; ++t) {
                const float4* w = (const float4*)(sm->w3 + (o + t) * 8);
                float4 wa = w[0], wb = w[1];
                float v = h2[0] * wa.x + h2[1] * wa.y + h2[2] * wa.z + h2[3] * wa.w
                        + h2[4] * wb.x + h2[5] * wb.y + h2[6] * wb.z + h2[7] * wb.w;
                vv[t] = fmaxf(fmaf(v, sm->s3[o + t], sm->b3[o + t]), 0.0f);
            }
            h3p[o / 2] = pack2(vv[0], vv[1]);
            if (part == 0)
                facc[8 + o / 2] = ffma2(h3p[o / 2], m3p, facc[8 + o / 2]);
        }
        // layer 4: this part's output range
#pragma unroll 1
        for (int o = obeg; o < oend; o += 2) {
            float vv[2];
#pragma unroll
            for (int t = 0; t < 2; ++t) {
                const ulonglong2* wrow = (const ulonglong2*)(sm->w4 + (o + t) * 16);
                ulonglong2 wa = wrow[0], wb = wrow[1], wc = wrow[2], wd = wrow[3];
                unsigned long long acc = ffma2(h3p[0], wa.x, 0ULL);
                acc = ffma2(h3p[1], wa.y, acc);
                acc = ffma2(h3p[2], wb.x, acc);
                acc = ffma2(h3p[3], wb.y, acc);
                acc = ffma2(h3p[4], wc.x, acc);
                acc = ffma2(h3p[5], wc.y, acc);
                acc = ffma2(h3p[6], wd.x, acc);
                acc = ffma2(h3p[7], wd.y, acc);
                float lo, hi; unpack2(acc, lo, hi);
                float v = lo + hi;
                vv[t] = fmaxf(fmaf(v, sm->s4[o + t], sm->b4[o + t]), 0.0f);
            }
            const int fi = (part ? (o - 16) : (o + 32)) >> 1;
            facc[fi] = ffma2(pack2(vv[0], vv[1]), m4p, facc[fi]);
        }
    }

    // mlp biases
    {
        const unsigned long long c3 = pack2(sm->mb[3], sm->mb[3]);
        if (part == 0) {
            const unsigned long long c0 = pack2(sm->mb[0], sm->mb[0]);
            const unsigned long long c1 = pack2(sm->mb[1], sm->mb[1]);
            const unsigned long long c2 = pack2(sm->mb[2], sm->mb[2]);
#pragma unroll
            for (int i = 0; i < 4; ++i)  facc[i]      = add2(facc[i], c0);
#pragma unroll
            for (int i = 0; i < 4; ++i)  facc[4 + i]  = add2(facc[4 + i], c1);
#pragma unroll
            for (int i = 0; i < 8; ++i)  facc[8 + i]  = add2(facc[8 + i], c2);
#pragma unroll
            for (int i = 0; i < 8; ++i)  facc[16 + i] = add2(facc[16 + i], c3);
        } else {
#pragma unroll
            for (int i = 0; i < 24; ++i) facc[i] = add2(facc[i], c3);
        }
    }

    ulonglong2* dst = (ulonglong2*)(g_feat + (size_t)gq * 48 + part * 24);
#pragma unroll
    for (int i = 0; i < 12; ++i)
        dst[i] = make_ulonglong2(facc[2 * i], facc[2 * i + 1]);
}

// ---------------------------------------------------------------------------
// Kernel 2b: final 96x96 GEMM + BN/ReLU + L2 normalize
// (byte-identical to rounds 6/7/8)
// ---------------------------------------------------------------------------
struct __align__(16) SmemGemm {
    float w5[9216];            // [96][96]
    float s5[96], b5[96];
};

extern "C" __global__ void __launch_bounds__(128)
gemm_kernel(const float* __restrict__ w5, const float* __restrict__ bn5,
            float* __restrict__ out) {
    extern __shared__ __align__(16) char smem_raw[];
    SmemGemm* sm = (SmemGemm*)smem_raw;

    const int tid = threadIdx.x;
    const int b   = blockIdx.y;

    for (int i = tid; i < 9216; i += 128) sm->w5[i] = w5[i];
    for (int i = tid; i < 96; i += 128) {
        float s = bn5[i] * rsqrtf(bn5[288 + i] + 1e-5f);
        sm->s5[i] = s; sm->b5[i] = bn5[96 + i] - bn5[192 + i] * s;
    }
    __syncthreads();

    const int half = tid & 1;
    const int n    = blockIdx.x * 64 + (tid >> 1);
    const int gq   = b * NPTS + n;

    unsigned long long fh[24];
    const ulonglong2* fsrc = (const ulonglong2*)(g_feat + (size_t)gq * 48 + half * 24);
#pragma unroll
    for (int i = 0; i < 12; ++i) {
        ulonglong2 t = fsrc[i];
        fh[2 * i] = t.x; fh[2 * i + 1] = t.y;
    }

    const int obase = half * 48;
    float* __restrict__ mybase = out + (size_t)gq * 96 + obase;
    float ss = 0.0f;

#pragma unroll 1
    for (int o = 0; o < 96; ++o) {
        const ulonglong2* wrow = (const ulonglong2*)(sm->w5 + o * 96 + half * 48);
        unsigned long long a0 = 0ULL, a1 = 0ULL;
#pragma unroll
        for (int j = 0; j < 12; ++j) {
            ulonglong2 w = wrow[j];
            a0 = ffma2(fh[2 * j],     w.x, a0);
            a1 = ffma2(fh[2 * j + 1], w.y, a1);
        }
        float lo, hi; unpack2(add2(a0, a1), lo, hi);
        float ph = lo + hi;
        float full = ph + __shfl_xor_sync(0xFFFFFFFFu, ph, 1);
        float v = fmaxf(fmaf(full, sm->s5[o], sm->b5[o]), 0.0f);
        ss = fmaf(v, v, ss);
        const int rel = o - obase;
        if ((unsigned)rel < 48u) mybase[rel] = v;   // unnormalized, own half
    }

    const float rn = rsqrtf(ss);
    float4* o4 = (float4*)mybase;
#pragma unroll 3
    for (int i = 0; i < 12; ++i) {
        float4 v = o4[i];
        v.x *= rn; v.y *= rn; v.z *= rn; v.w *= rn;
        o4[i] = v;
    }
}

// ---------------------------------------------------------------------------
// launch
// ---------------------------------------------------------------------------
extern "C" void kernel_launch(void* const* d_in, const int* in_sizes, int n_in,
                              void* d_out, int out_size) {
    const float* x   = (const float*)d_in[0];
    const float* w1  = (const float*)d_in[1];
    const float* w2  = (const float*)d_in[2];
    const float* w3  = (const float*)d_in[3];
    const float* w4  = (const float*)d_in[4];
    const float* w5  = (const float*)d_in[5];
    const float* mw  = (const float*)d_in[6];
    const float* mb  = (const float*)d_in[7];
    const float* bn1 = (const float*)d_in[8];
    const float* bn2 = (const float*)d_in[9];
    const float* bn3 = (const float*)d_in[10];
    const float* bn4 = (const float*)d_in[11];
    const float* bn5 = (const float*)d_in[12];

    const size_t knn_smem  = NPTS * 12 + 3 * 64 * 17 * 8 + 256 * QCAP * 4; // ~89.5KB
    const size_t pool_smem = sizeof(SmemPool);            // ~38.8KB
    const size_t gemm_smem = sizeof(SmemGemm);            // ~37.6KB

    cudaFuncSetAttribute(knn_kernel,  cudaFuncAttributeMaxDynamicSharedMemorySize, (int)knn_smem);
    cudaFuncSetAttribute(pool_kernel, cudaFuncAttributeMaxDynamicSharedMemorySize, (int)pool_smem);
    cudaFuncSetAttribute(gemm_kernel, cudaFuncAttributeMaxDynamicSharedMemorySize, (int)gemm_smem);

    dim3 grid(NPTS / 64, BATCH);   // 64 x 8 = 512 blocks
    knn_kernel<<<grid, 256, knn_smem>>>(x);
    pool_kernel<<<grid, 128, pool_smem>>>(x, w1, w2, w3, w4, mw, mb,
                                          bn1, bn2, bn3, bn4);
    gemm_kernel<<<grid, 128, gemm_smem>>>(w5, bn5, (float*)d_out);
}